// round 3
// baseline (speedup 1.0000x reference)
#include <cuda_runtime.h>
#include <cuda_bf16.h>
#include <math.h>
#include <stdint.h>

#define BB   8
#define LL   2048
#define DD   256
#define DIN_ 512
#define NN   64
#define PP   64
#define HH   8
#define ROWS (BB*LL)          // 16384
#define XPROJ (HH + 2*NN)     // 136

// ---------------- scratch (device globals) ---------------------------------
__device__ __nv_bfloat16 g_xh[ROWS*DD],   g_xl[ROWS*DD];     // LN1 out hi/lo
__device__ float         g_ur [ROWS*DIN_];                   // GEMM1 out
__device__ float         g_u  [ROWS*DIN_];                   // gelu(conv)
__device__ __nv_bfloat16 g_uh[ROWS*DIN_], g_ul[ROWS*DIN_];   // gelu hi/lo
__device__ float         g_dbc[ROWS*XPROJ];
__device__ float         g_dtd[ROWS*HH*2];                   // {dt, decay}
__device__ float         g_yc [ROWS*DIN_];
__device__ __nv_bfloat16 g_yh[ROWS*DIN_], g_yl[ROWS*DIN_];   // oln hi/lo
// transposed+split weights: Wt[n*K + k]
__device__ __nv_bfloat16 g_w1h[DIN_*DD],   g_w1l[DIN_*DD];    // W_in^T  (N=512,K=256)
__device__ __nv_bfloat16 g_w2h[XPROJ*DIN_],g_w2l[XPROJ*DIN_]; // W_xproj^T (N=136,K=512)
__device__ __nv_bfloat16 g_w3h[DD*DIN_],   g_w3l[DD*DIN_];    // W_out^T (N=256,K=512)

// ---------------- helpers ---------------------------------------------------
__device__ __forceinline__ uint32_t smem_u32(const void* p){
    uint32_t a;
    asm("{ .reg .u64 t; cvta.to.shared.u64 t, %1; cvt.u32.u64 %0, t; }" : "=r"(a) : "l"(p));
    return a;
}
__device__ __forceinline__ void cp16(uint32_t dst, const void* src, int sz){
    asm volatile("cp.async.ca.shared.global [%0], [%1], 16, %2;"
                 :: "r"(dst), "l"(src), "r"(sz) : "memory");
}
#define CP_COMMIT() asm volatile("cp.async.commit_group;" ::: "memory")
#define CP_WAIT1()  asm volatile("cp.async.wait_group 1;" ::: "memory")
#define CP_WAIT0()  asm volatile("cp.async.wait_group 0;" ::: "memory")

__device__ __forceinline__ void mma_bf16(float* d, const uint32_t* a, const uint32_t* b){
    asm volatile("mma.sync.aligned.m16n8k16.row.col.f32.bf16.bf16.f32 "
        "{%0,%1,%2,%3}, {%4,%5,%6,%7}, {%8,%9}, {%0,%1,%2,%3};"
        : "+f"(d[0]), "+f"(d[1]), "+f"(d[2]), "+f"(d[3])
        : "r"(a[0]), "r"(a[1]), "r"(a[2]), "r"(a[3]), "r"(b[0]), "r"(b[1]));
}

// f32x2 packed math (compiles under compute_103)
#define PK2(d, lo, hi) asm("mov.b64 %0, {%1,%2};" : "=l"(d) : "r"(__float_as_uint(lo)), "r"(__float_as_uint(hi)))
#define UPK2(lo, hi, v) do { uint32_t _a,_b; asm("mov.b64 {%0,%1}, %2;" : "=r"(_a), "=r"(_b) : "l"(v)); lo=__uint_as_float(_a); hi=__uint_as_float(_b); } while(0)
#define F2MUL(d, a, b)    asm("mul.rn.f32x2 %0, %1, %2;"     : "=l"(d) : "l"(a), "l"(b))
#define F2FMA(d, a, b, c) asm("fma.rn.f32x2 %0, %1, %2, %3;" : "=l"(d) : "l"(a), "l"(b), "l"(c))

// ---------------- weight prep: transpose + bf16 hi/lo split ----------------
__global__ __launch_bounds__(256) void wprep(const float* __restrict__ W,
        __nv_bfloat16* __restrict__ oh, __nv_bfloat16* __restrict__ ol, int K, int N)
{
    int idx = blockIdx.x * 256 + threadIdx.x;
    if (idx >= K * N) return;
    int n = idx / K, k = idx - n * K;
    float v = W[(size_t)k * N + n];
    __nv_bfloat16 hh = __float2bfloat16(v);
    oh[idx] = hh;
    ol[idx] = __float2bfloat16(v - __bfloat162float(hh));
}

// ---------------- LayerNorm -> bf16 hi/lo ----------------------------------
template<int W>
__global__ __launch_bounds__(256) void ln_bf(const float* __restrict__ x,
        const float* __restrict__ w, const float* __restrict__ b,
        __nv_bfloat16* __restrict__ yh, __nv_bfloat16* __restrict__ yl)
{
    constexpr int E = W / 256;
    int row = blockIdx.x;
    const float* xr = x + (size_t)row * W;
    float v[E]; float s = 0.f, q = 0.f;
#pragma unroll
    for (int i = 0; i < E; i++) { v[i] = xr[threadIdx.x + 256*i]; s += v[i]; q += v[i]*v[i]; }
#pragma unroll
    for (int o = 16; o; o >>= 1) {
        s += __shfl_xor_sync(0xffffffffu, s, o);
        q += __shfl_xor_sync(0xffffffffu, q, o);
    }
    __shared__ float rs[8], rq[8];
    if ((threadIdx.x & 31) == 0) { rs[threadIdx.x>>5] = s; rq[threadIdx.x>>5] = q; }
    __syncthreads();
    float S = 0.f, Q = 0.f;
#pragma unroll
    for (int i = 0; i < 8; i++) { S += rs[i]; Q += rq[i]; }
    float mean = S / (float)W;
    float rstd = rsqrtf(Q / (float)W - mean*mean + 1e-5f);
#pragma unroll
    for (int i = 0; i < E; i++) {
        int c = threadIdx.x + 256*i;
        float o = (v[i] - mean) * rstd * w[c] + b[c];
        __nv_bfloat16 hh = __float2bfloat16(o);
        yh[(size_t)row*W + c] = hh;
        yl[(size_t)row*W + c] = __float2bfloat16(o - __bfloat162float(hh));
    }
}

// ---------------- bf16-split GEMM via mma.sync (HMMA) ----------------------
// C[M,N] = Ahi@Bhi + Ahi@Blo + Alo@Bhi (+addend). fp32 accum.
// A: bf16 [M,K] row-major. B: bf16 [N,K] row-major (weights pre-transposed).
// CTA 128x128x32, 8 warps (4x2), warp tile 32x64. cp.async double buffer.
// SMEM row stride 40 bf16 (80B): 16B-aligned for cp.async, conflict-free LDS.
#define SKB   40            // smem row stride in bf16
#define MATB  10240         // 128*80 bytes per matrix
#define STAGEB 40960        // 4 matrices
__global__ __launch_bounds__(256,2) void hgemm(
    const __nv_bfloat16* __restrict__ Ah, const __nv_bfloat16* __restrict__ Al,
    const __nv_bfloat16* __restrict__ Bh, const __nv_bfloat16* __restrict__ Bl,
    float* __restrict__ C, const float* __restrict__ addend,
    int M, int N, int K)
{
    extern __shared__ char smem[];
    const uint32_t sbase = smem_u32(smem);
    const int tid = threadIdx.x;
    const int wid = tid >> 5, lane = tid & 31;
    const int g = lane >> 2, tg = lane & 3;
    const int m0 = blockIdx.x * 128, n0 = blockIdx.y * 128;
    const int NC = K >> 5;
    const int wm = (wid >> 1) * 32, wn = (wid & 1) * 64;

    float acc[2][8][4];
#pragma unroll
    for (int i = 0; i < 2; i++)
#pragma unroll
        for (int j = 0; j < 8; j++)
#pragma unroll
            for (int q = 0; q < 4; q++) acc[i][j][q] = 0.f;

    // per-thread load assignment: 8 chunks of 16B
    // idx = tid + i*256 ; mat = idx>>9 (0:Ah 1:Al 2:Bh 3:Bl); w=idx&511: row=w>>2, kc=w&3
    auto issue = [&](int c){
        int s = c & 1;
        int k0 = c << 5;
#pragma unroll
        for (int i = 0; i < 8; i++) {
            int idx = tid + i * 256;
            int mat = idx >> 9, w = idx & 511, row = w >> 2, kc = w & 3;
            uint32_t dst = sbase + s*STAGEB + mat*MATB + row*80 + kc*16;
            const __nv_bfloat16* src;
            int sz = 16;
            if (mat == 0)      src = Ah + (size_t)(m0 + row) * K + k0 + kc*8;
            else if (mat == 1) src = Al + (size_t)(m0 + row) * K + k0 + kc*8;
            else {
                int n = n0 + row;
                int vld = (n < N);
                const __nv_bfloat16* Bp = (mat == 2) ? Bh : Bl;
                src = Bp + (size_t)(vld ? n : 0) * K + k0 + kc*8;
                sz = vld ? 16 : 0;
            }
            cp16(dst, src, sz);
        }
    };

    issue(0); CP_COMMIT();

    for (int c = 0; c < NC; c++) {
        int s = c & 1;
        if (c + 1 < NC) { issue(c + 1); CP_COMMIT(); CP_WAIT1(); }
        else            { CP_WAIT0(); }
        __syncthreads();

        const char* st = smem + s * STAGEB;
#pragma unroll
        for (int ks = 0; ks < 32; ks += 16) {
            // B fragments: 8 n-atoms x 2 regs, hi & lo
            uint32_t bh[8][2], bl[8][2];
#pragma unroll
            for (int j = 0; j < 8; j++) {
                int row = wn + j*8 + g;
                int kb = (ks + tg*2) * 2;
                bh[j][0] = *(const uint32_t*)(st + 2*MATB + row*80 + kb);
                bh[j][1] = *(const uint32_t*)(st + 2*MATB + row*80 + kb + 16);
                bl[j][0] = *(const uint32_t*)(st + 3*MATB + row*80 + kb);
                bl[j][1] = *(const uint32_t*)(st + 3*MATB + row*80 + kb + 16);
            }
#pragma unroll
            for (int i = 0; i < 2; i++) {
                int r0 = wm + i*16 + g;
                int kb = (ks + tg*2) * 2;
                uint32_t ah[4], al[4];
                ah[0] = *(const uint32_t*)(st + (r0    )*80 + kb);
                ah[1] = *(const uint32_t*)(st + (r0 + 8)*80 + kb);
                ah[2] = *(const uint32_t*)(st + (r0    )*80 + kb + 16);
                ah[3] = *(const uint32_t*)(st + (r0 + 8)*80 + kb + 16);
                al[0] = *(const uint32_t*)(st + MATB + (r0    )*80 + kb);
                al[1] = *(const uint32_t*)(st + MATB + (r0 + 8)*80 + kb);
                al[2] = *(const uint32_t*)(st + MATB + (r0    )*80 + kb + 16);
                al[3] = *(const uint32_t*)(st + MATB + (r0 + 8)*80 + kb + 16);
#pragma unroll
                for (int j = 0; j < 8; j++) {
                    mma_bf16(acc[i][j], ah, bh[j]);
                    mma_bf16(acc[i][j], ah, bl[j]);
                    mma_bf16(acc[i][j], al, bh[j]);
                }
            }
        }
        __syncthreads();
    }

    // epilogue
#pragma unroll
    for (int i = 0; i < 2; i++) {
#pragma unroll
        for (int j = 0; j < 8; j++) {
            int col = n0 + wn + j*8 + tg*2;
            if (col >= N) continue;
            int mA = m0 + wm + i*16 + g;
            int mB = mA + 8;
            float2 v0 = make_float2(acc[i][j][0], acc[i][j][1]);
            float2 v1 = make_float2(acc[i][j][2], acc[i][j][3]);
            if (addend) {
                float2 a0 = *(const float2*)(addend + (size_t)mA * N + col);
                float2 a1 = *(const float2*)(addend + (size_t)mB * N + col);
                v0.x += a0.x; v0.y += a0.y; v1.x += a1.x; v1.y += a1.y;
            }
            *(float2*)(C + (size_t)mA * N + col) = v0;
            *(float2*)(C + (size_t)mB * N + col) = v1;
        }
    }
}

// ---------------- depthwise conv3 + GELU -> fp32 + bf16 hi/lo --------------
__global__ __launch_bounds__(256) void convgelu_k(const float* __restrict__ cw,
                                                  const float* __restrict__ cb)
{
    int idx = blockIdx.x * 256 + threadIdx.x;
    if (idx >= ROWS * DIN_) return;
    int c = idx & (DIN_ - 1);
    int l = (idx >> 9) & (LL - 1);
    float w0 = cw[c*3], w1 = cw[c*3+1], w2 = cw[c*3+2];
    float x = g_ur[idx] * w1 + cb[c];
    if (l > 0)      x += g_ur[idx - DIN_] * w0;
    if (l < LL - 1) x += g_ur[idx + DIN_] * w2;
    float g = 0.5f * x * (1.f + erff(x * 0.7071067811865476f));
    g_u[idx] = g;
    __nv_bfloat16 hh = __float2bfloat16(g);
    g_uh[idx] = hh;
    g_ul[idx] = __float2bfloat16(g - __bfloat162float(hh));
}

// ---------------- dt/decay prep --------------------------------------------
__global__ __launch_bounds__(256) void dtprep_k(const float* __restrict__ dt_bias,
                                                const float* __restrict__ A_log)
{
    int i = blockIdx.x * 256 + threadIdx.x;
    if (i >= ROWS * HH) return;
    int h = i & 7;
    int row = i >> 3;
    float xx = g_dbc[(size_t)row * XPROJ + h] + dt_bias[h];
    float dt = (xx > 20.f) ? xx : log1pf(expf(xx));
    float dec = expf(-dt * expf(A_log[h]));
    g_dtd[2*i]     = dt;
    g_dtd[2*i + 1] = dec;
}

// ---------------- selective scan: f32x2 + pipelined shfl reduction ---------
__global__ __launch_bounds__(256) void scan_k(const float* __restrict__ Ds)
{
    int blk = blockIdx.x;
    int pc = blk & 1, h = (blk >> 1) & 7, b = blk >> 4;
    int pl = threadIdx.x >> 3, ng = threadIdx.x & 7;
    int p = pc * 32 + pl, nb = ng * 8;
    float dsh = Ds[h];

    const float* dtd = g_dtd + ((size_t)(b * LL) * HH + h) * 2;
    const float* up  = g_u   + (size_t)(b * LL) * DIN_ + h*64 + p;
    const float* bp  = g_dbc + (size_t)(b * LL) * XPROJ + 8  + nb;
    const float* cp  = g_dbc + (size_t)(b * LL) * XPROJ + 72 + nb;
    float*       yp  = g_yc  + (size_t)(b * LL) * DIN_ + h*64 + p;

    unsigned long long hs[4] = {0ull,0ull,0ull,0ull};

    float2 dv = *(const float2*)dtd;
    float  xv = *up;
    ulonglong2 B0 = *(const ulonglong2*)bp, B1 = *(const ulonglong2*)(bp + 4);
    ulonglong2 C0 = *(const ulonglong2*)cp, C1 = *(const ulonglong2*)(cp + 4);

    float a0=0.f, a1=0.f, a2=0.f, x0=0.f, x1=0.f, x2=0.f;
    for (int l = 0; l < LL + 3; l++) {
        float alocal = 0.f, xvc = 0.f;
        if (l < LL) {
            float2 dvc = dv; xvc = xv;
            unsigned long long b2[4] = {B0.x, B0.y, B1.x, B1.y};
            unsigned long long c2[4] = {C0.x, C0.y, C1.x, C1.y};
            if (l + 1 < LL) {
                dtd += HH*2; up += DIN_; bp += XPROJ; cp += XPROJ;
                dv = *(const float2*)dtd; xv = *up;
                B0 = *(const ulonglong2*)bp; B1 = *(const ulonglong2*)(bp + 4);
                C0 = *(const ulonglong2*)cp; C1 = *(const ulonglong2*)(cp + 4);
            }
            float dtx = dvc.x * xvc;
            unsigned long long dec2, dtx2, acc2 = 0ull;
            PK2(dec2, dvc.y, dvc.y);
            PK2(dtx2, dtx, dtx);
#pragma unroll
            for (int j = 0; j < 4; j++) {
                unsigned long long t;
                F2MUL(t, dtx2, b2[j]);
                F2FMA(hs[j], hs[j], dec2, t);
                F2FMA(acc2, hs[j], c2[j], acc2);
            }
            float alo, ahi; UPK2(alo, ahi, acc2);
            alocal = alo + ahi;
        }
        float y3 = a2 + __shfl_xor_sync(0xffffffffu, a2, 4);
        float n2 = a1 + __shfl_xor_sync(0xffffffffu, a1, 2);
        float n1 = a0 + __shfl_xor_sync(0xffffffffu, a0, 1);
        if (l >= 3) {
            if (ng == 0) yp[0] = y3 + dsh * x2;
            yp += DIN_;
        }
        a2 = n2; a1 = n1; a0 = alocal;
        x2 = x1; x1 = x0; x0 = xvc;
    }
}

// ---------------- launch ----------------------------------------------------
extern "C" void kernel_launch(void* const* d_in, const int* in_sizes, int n_in,
                              void* d_out, int out_size)
{
    const float* src     = (const float*)d_in[0];
    const float* ln_w    = (const float*)d_in[1];
    const float* ln_b    = (const float*)d_in[2];
    const float* W_in    = (const float*)d_in[3];
    const float* conv_w  = (const float*)d_in[4];
    const float* conv_b  = (const float*)d_in[5];
    const float* W_xproj = (const float*)d_in[6];
    const float* dt_bias = (const float*)d_in[7];
    const float* A_log   = (const float*)d_in[8];
    const float* Ds      = (const float*)d_in[9];
    const float* oln_w   = (const float*)d_in[10];
    const float* oln_b   = (const float*)d_in[11];
    const float* W_out   = (const float*)d_in[12];
    float* out = (float*)d_out;

    __nv_bfloat16 *p_xh,*p_xl,*p_uh,*p_ul,*p_yh,*p_yl;
    __nv_bfloat16 *p_w1h,*p_w1l,*p_w2h,*p_w2l,*p_w3h,*p_w3l;
    float *p_ur,*p_dbc,*p_yc;
    cudaGetSymbolAddress((void**)&p_xh, g_xh);   cudaGetSymbolAddress((void**)&p_xl, g_xl);
    cudaGetSymbolAddress((void**)&p_uh, g_uh);   cudaGetSymbolAddress((void**)&p_ul, g_ul);
    cudaGetSymbolAddress((void**)&p_yh, g_yh);   cudaGetSymbolAddress((void**)&p_yl, g_yl);
    cudaGetSymbolAddress((void**)&p_w1h, g_w1h); cudaGetSymbolAddress((void**)&p_w1l, g_w1l);
    cudaGetSymbolAddress((void**)&p_w2h, g_w2h); cudaGetSymbolAddress((void**)&p_w2l, g_w2l);
    cudaGetSymbolAddress((void**)&p_w3h, g_w3h); cudaGetSymbolAddress((void**)&p_w3l, g_w3l);
    cudaGetSymbolAddress((void**)&p_ur, g_ur);
    cudaGetSymbolAddress((void**)&p_dbc, g_dbc);
    cudaGetSymbolAddress((void**)&p_yc, g_yc);

    const int GSMEM = 2 * STAGEB;   // 81920
    cudaFuncSetAttribute(hgemm, cudaFuncAttributeMaxDynamicSharedMemorySize, GSMEM);

    // weight prep (transpose + split)
    wprep<<<(DD*DIN_ + 255)/256, 256>>>(W_in,    p_w1h, p_w1l, DD,   DIN_);
    wprep<<<(DIN_*XPROJ + 255)/256, 256>>>(W_xproj, p_w2h, p_w2l, DIN_, XPROJ);
    wprep<<<(DIN_*DD + 255)/256, 256>>>(W_out,   p_w3h, p_w3l, DIN_, DD);

    // 1) LN1 -> bf16 hi/lo
    ln_bf<DD><<<ROWS, 256>>>(src, ln_w, ln_b, p_xh, p_xl);
    // 2) ur = x @ W_in
    hgemm<<<dim3(ROWS/128, 4), 256, GSMEM>>>(p_xh, p_xl, p_w1h, p_w1l, p_ur, nullptr,
                                             ROWS, DIN_, DD);
    // 3) u = gelu(conv3(ur)+b)
    convgelu_k<<<(ROWS*DIN_)/256, 256>>>(conv_w, conv_b);
    // 4) dbc = u @ W_xproj
    hgemm<<<dim3(ROWS/128, 2), 256, GSMEM>>>(p_uh, p_ul, p_w2h, p_w2l, p_dbc, nullptr,
                                             ROWS, XPROJ, DIN_);
    // 5) dt/decay
    dtprep_k<<<(ROWS*HH)/256, 256>>>(dt_bias, A_log);
    // 6) scan
    scan_k<<<BB*HH*2, 256>>>(Ds);
    // 7) oln -> bf16 hi/lo
    ln_bf<DIN_><<<ROWS, 256>>>(p_yc, oln_w, oln_b, p_yh, p_yl);
    // 8) out = src + yln @ W_out
    hgemm<<<dim3(ROWS/128, 2), 256, GSMEM>>>(p_yh, p_yl, p_w3h, p_w3l, out, src,
                                             ROWS, DD, DIN_);
}

// round 4
// speedup vs baseline: 1.1100x; 1.1100x over previous
#include <cuda_runtime.h>
#include <math.h>
#include <stdint.h>

#define BB   8
#define LL   2048
#define DD   256
#define DIN_ 512
#define NN   64
#define PP   64
#define HH   8
#define ROWS (BB*LL)          // 16384
#define XPROJ (HH + 2*NN)     // 136

// ---------------- scratch (device globals) ---------------------------------
__device__ float g_xln[ROWS*DD];
__device__ float g_ur [ROWS*DIN_];
__device__ float g_u  [ROWS*DIN_];
__device__ float g_dbc[ROWS*XPROJ];
__device__ float g_dtd[ROWS*HH*2];      // {dt, decay}
__device__ float g_yc [ROWS*DIN_];
__device__ float g_yln[ROWS*DIN_];

// ---------------- helpers ---------------------------------------------------
__device__ __forceinline__ uint32_t smem_u32(const void* p){
    uint32_t a;
    asm("{ .reg .u64 t; cvta.to.shared.u64 t, %1; cvt.u32.u64 %0, t; }" : "=r"(a) : "l"(p));
    return a;
}
__device__ __forceinline__ void cp16(uint32_t dst, const void* src, int sz){
    asm volatile("cp.async.ca.shared.global [%0], [%1], 16, %2;"
                 :: "r"(dst), "l"(src), "r"(sz) : "memory");
}
#define CP_COMMIT() asm volatile("cp.async.commit_group;" ::: "memory")
#define CP_WAIT1()  asm volatile("cp.async.wait_group 1;" ::: "memory")
#define CP_WAIT0()  asm volatile("cp.async.wait_group 0;" ::: "memory")

// f32x2 packed math
#define PK2(d, lo, hi) asm("mov.b64 %0, {%1,%2};" : "=l"(d) : "r"(__float_as_uint(lo)), "r"(__float_as_uint(hi)))
#define UPK2(lo, hi, v) do { uint32_t _a,_b; asm("mov.b64 {%0,%1}, %2;" : "=r"(_a), "=r"(_b) : "l"(v)); lo=__uint_as_float(_a); hi=__uint_as_float(_b); } while(0)
#define F2MUL(d, a, b)    asm("mul.rn.f32x2 %0, %1, %2;"     : "=l"(d) : "l"(a), "l"(b))
#define F2FMA(d, a, b, c) asm("fma.rn.f32x2 %0, %1, %2, %3;" : "=l"(d) : "l"(a), "l"(b), "l"(c))

// ---------------- LayerNorm --------------------------------------------------
template<int W>
__global__ __launch_bounds__(256) void ln_kernel(const float* __restrict__ x,
        const float* __restrict__ w, const float* __restrict__ b,
        float* __restrict__ y)
{
    constexpr int E = W / 256;
    int row = blockIdx.x;
    const float* xr = x + (size_t)row * W;
    float v[E]; float s = 0.f, q = 0.f;
#pragma unroll
    for (int i = 0; i < E; i++) { v[i] = xr[threadIdx.x + 256*i]; s += v[i]; q += v[i]*v[i]; }
#pragma unroll
    for (int o = 16; o; o >>= 1) {
        s += __shfl_xor_sync(0xffffffffu, s, o);
        q += __shfl_xor_sync(0xffffffffu, q, o);
    }
    __shared__ float rs[8], rq[8];
    if ((threadIdx.x & 31) == 0) { rs[threadIdx.x>>5] = s; rq[threadIdx.x>>5] = q; }
    __syncthreads();
    float S = 0.f, Q = 0.f;
#pragma unroll
    for (int i = 0; i < 8; i++) { S += rs[i]; Q += rq[i]; }
    float mean = S / (float)W;
    float rstd = rsqrtf(Q / (float)W - mean*mean + 1e-5f);
    float* yr = y + (size_t)row * W;
#pragma unroll
    for (int i = 0; i < E; i++) {
        int c = threadIdx.x + 256*i;
        yr[c] = (v[i] - mean) * rstd * w[c] + b[c];
    }
}

// ---------------- fp32 SGEMM v2: 128x128x16, cp.async double buffer ---------
// A[M,K] row-major, B[K,N] row-major. 256 threads, 8x8 per thread in 4-wide
// split strips (m: ty*4 / 64+ty*4 ; n: tx*4 / 64+tx*4).
#define ASTRIDE 20          // floats per A smem row (80B, 16B aligned)
__global__ __launch_bounds__(256) void sgemm2(
    const float* __restrict__ A, const float* __restrict__ B,
    float* __restrict__ C, const float* __restrict__ addend,
    int M, int N, int K)
{
    __shared__ float As[2][128*ASTRIDE];
    __shared__ float Bs[2][16*128];
    const int tid = threadIdx.x;
    const int tx = tid & 15, ty = tid >> 4;
    const int m0 = blockIdx.x * 128, n0 = blockIdx.y * 128;
    const int NC = K >> 4;
    const uint32_t asb = smem_u32(As), bsb = smem_u32(Bs);

    float acc[8][8];
#pragma unroll
    for (int i = 0; i < 8; i++)
#pragma unroll
        for (int j = 0; j < 8; j++) acc[i][j] = 0.f;

    auto issue = [&](int c){
        int s = c & 1;
        int k0 = c << 4;
        // A: 512 chunks of 16B: id -> r=id>>2 (0..127), cc=id&3
#pragma unroll
        for (int t = 0; t < 2; t++) {
            int id = tid + t * 256;
            int r = id >> 2, cc = id & 3;
            cp16(asb + s*10240 + r*80 + cc*16,
                 A + (size_t)(m0 + r) * K + k0 + cc*4, 16);
        }
        // B: 512 chunks: id -> k=id>>5 (0..15), n4=id&31
#pragma unroll
        for (int t = 0; t < 2; t++) {
            int id = tid + t * 256;
            int k = id >> 5, n4 = id & 31;
            int n = n0 + n4 * 4;
            int ok = (n + 4 <= N);
            cp16(bsb + s*8192 + k*512 + n4*16,
                 B + (size_t)(k0 + k) * N + (ok ? n : 0), ok ? 16 : 0);
        }
    };

    issue(0); CP_COMMIT();

    for (int c = 0; c < NC; c++) {
        int s = c & 1;
        if (c + 1 < NC) { issue(c + 1); CP_COMMIT(); CP_WAIT1(); }
        else            { CP_WAIT0(); }
        __syncthreads();
        const float* as = As[s];
        const float* bs = Bs[s];
#pragma unroll
        for (int kk = 0; kk < 16; kk++) {
            float a[8], b[8];
#pragma unroll
            for (int i = 0; i < 4; i++) {
                a[i]     = as[(ty*4 + i) * ASTRIDE + kk];
                a[4 + i] = as[(64 + ty*4 + i) * ASTRIDE + kk];
            }
            float4 b0 = *(const float4*)&bs[kk*128 + tx*4];
            float4 b1 = *(const float4*)&bs[kk*128 + 64 + tx*4];
            b[0]=b0.x; b[1]=b0.y; b[2]=b0.z; b[3]=b0.w;
            b[4]=b1.x; b[5]=b1.y; b[6]=b1.z; b[7]=b1.w;
#pragma unroll
            for (int i = 0; i < 8; i++)
#pragma unroll
                for (int j = 0; j < 8; j++)
                    acc[i][j] = fmaf(a[i], b[j], acc[i][j]);
        }
        __syncthreads();
    }

    // epilogue: two 4-wide n strips per thread
#pragma unroll
    for (int i = 0; i < 8; i++) {
        int m = m0 + ((i < 4) ? (ty*4 + i) : (64 + ty*4 + i - 4));
#pragma unroll
        for (int js = 0; js < 2; js++) {
            int col = n0 + js*64 + tx*4;
            if (col + 4 > N) continue;
            float4 v = make_float4(acc[i][js*4+0], acc[i][js*4+1],
                                   acc[i][js*4+2], acc[i][js*4+3]);
            if (addend) {
                float4 ad = *(const float4*)(addend + (size_t)m * N + col);
                v.x += ad.x; v.y += ad.y; v.z += ad.z; v.w += ad.w;
            }
            *(float4*)(C + (size_t)m * N + col) = v;
        }
    }
}

// ---------------- depthwise conv3 + exact GELU ------------------------------
__global__ __launch_bounds__(256) void convgelu_k(const float* __restrict__ cw,
                                                  const float* __restrict__ cb)
{
    int idx = blockIdx.x * 256 + threadIdx.x;
    if (idx >= ROWS * DIN_) return;
    int c = idx & (DIN_ - 1);
    int l = (idx >> 9) & (LL - 1);
    float w0 = cw[c*3], w1 = cw[c*3+1], w2 = cw[c*3+2];
    float x = g_ur[idx] * w1 + cb[c];
    if (l > 0)      x += g_ur[idx - DIN_] * w0;
    if (l < LL - 1) x += g_ur[idx + DIN_] * w2;
    g_u[idx] = 0.5f * x * (1.f + erff(x * 0.7071067811865476f));
}

// ---------------- dt/decay prep ---------------------------------------------
__global__ __launch_bounds__(256) void dtprep_k(const float* __restrict__ dt_bias,
                                                const float* __restrict__ A_log)
{
    int i = blockIdx.x * 256 + threadIdx.x;
    if (i >= ROWS * HH) return;
    int h = i & 7;
    int row = i >> 3;
    float xx = g_dbc[(size_t)row * XPROJ + h] + dt_bias[h];
    float dt = (xx > 20.f) ? xx : log1pf(expf(xx));
    float dec = expf(-dt * expf(A_log[h]));
    g_dtd[2*i]     = dt;
    g_dtd[2*i + 1] = dec;
}

// ---------------- selective scan: depth-4 register ring prefetch ------------
__global__ __launch_bounds__(256) void scan_k(const float* __restrict__ Ds)
{
    int blk = blockIdx.x;
    int pc = blk & 1, h = (blk >> 1) & 7, b = blk >> 4;
    int pl = threadIdx.x >> 3, ng = threadIdx.x & 7;
    int p = pc * 32 + pl, nb = ng * 8;
    float dsh = Ds[h];

    const float* dtd = g_dtd + ((size_t)(b * LL) * HH + h) * 2;
    const float* up  = g_u   + (size_t)(b * LL) * DIN_ + h*64 + p;
    const float* bp  = g_dbc + (size_t)(b * LL) * XPROJ + 8  + nb;
    const float* cpp = g_dbc + (size_t)(b * LL) * XPROJ + 72 + nb;
    float*       yp  = g_yc  + (size_t)(b * LL) * DIN_ + h*64 + p;

    unsigned long long hs[4] = {0ull,0ull,0ull,0ull};
    float2 dvb[4]; float xvb[4];
    ulonglong2 Bb[4][2], Cb[4][2];

#define LOADQ(slot, l) do { \
    size_t _l = (size_t)(l); \
    dvb[slot] = *(const float2*)(dtd + _l*(HH*2)); \
    xvb[slot] = up[_l*DIN_]; \
    Bb[slot][0] = *(const ulonglong2*)(bp + _l*XPROJ); \
    Bb[slot][1] = *(const ulonglong2*)(bp + _l*XPROJ + 4); \
    Cb[slot][0] = *(const ulonglong2*)(cpp + _l*XPROJ); \
    Cb[slot][1] = *(const ulonglong2*)(cpp + _l*XPROJ + 4); \
  } while(0)

    LOADQ(0, 0); LOADQ(1, 1); LOADQ(2, 2);

    float a0=0.f, a1=0.f, a2=0.f, x0=0.f, x1=0.f, x2=0.f;
    for (int lb = 0; lb < LL + 4; lb += 4) {
#pragma unroll
        for (int q = 0; q < 4; q++) {
            int l = lb + q;
            float alocal = 0.f, xvc = 0.f;
            if (l < LL) {
                if (l + 3 < LL) LOADQ((q + 3) & 3, l + 3);
                float2 dvc = dvb[q]; xvc = xvb[q];
                unsigned long long b2[4] = {Bb[q][0].x, Bb[q][0].y, Bb[q][1].x, Bb[q][1].y};
                unsigned long long c2[4] = {Cb[q][0].x, Cb[q][0].y, Cb[q][1].x, Cb[q][1].y};
                float dtx = dvc.x * xvc;
                unsigned long long dec2, dtx2, acc2 = 0ull;
                PK2(dec2, dvc.y, dvc.y);
                PK2(dtx2, dtx, dtx);
#pragma unroll
                for (int j = 0; j < 4; j++) {
                    unsigned long long t;
                    F2MUL(t, dtx2, b2[j]);
                    F2FMA(hs[j], hs[j], dec2, t);
                    F2FMA(acc2, hs[j], c2[j], acc2);
                }
                float alo, ahi; UPK2(alo, ahi, acc2);
                alocal = alo + ahi;
            }
            float y3 = a2 + __shfl_xor_sync(0xffffffffu, a2, 4);
            float n2 = a1 + __shfl_xor_sync(0xffffffffu, a1, 2);
            float n1 = a0 + __shfl_xor_sync(0xffffffffu, a0, 1);
            if (l >= 3 && l < LL + 3) {
                if (ng == 0) yp[0] = y3 + dsh * x2;
                yp += DIN_;
            }
            a2 = n2; a1 = n1; a0 = alocal;
            x2 = x1; x1 = x0; x0 = xvc;
        }
    }
#undef LOADQ
}

// ---------------- launch ----------------------------------------------------
extern "C" void kernel_launch(void* const* d_in, const int* in_sizes, int n_in,
                              void* d_out, int out_size)
{
    const float* src     = (const float*)d_in[0];
    const float* ln_w    = (const float*)d_in[1];
    const float* ln_b    = (const float*)d_in[2];
    const float* W_in    = (const float*)d_in[3];
    const float* conv_w  = (const float*)d_in[4];
    const float* conv_b  = (const float*)d_in[5];
    const float* W_xproj = (const float*)d_in[6];
    const float* dt_bias = (const float*)d_in[7];
    const float* A_log   = (const float*)d_in[8];
    const float* Ds      = (const float*)d_in[9];
    const float* oln_w   = (const float*)d_in[10];
    const float* oln_b   = (const float*)d_in[11];
    const float* W_out   = (const float*)d_in[12];
    float* out = (float*)d_out;

    float *p_xln, *p_ur, *p_u, *p_dbc, *p_yc, *p_yln;
    cudaGetSymbolAddress((void**)&p_xln, g_xln);
    cudaGetSymbolAddress((void**)&p_ur,  g_ur);
    cudaGetSymbolAddress((void**)&p_u,   g_u);
    cudaGetSymbolAddress((void**)&p_dbc, g_dbc);
    cudaGetSymbolAddress((void**)&p_yc,  g_yc);
    cudaGetSymbolAddress((void**)&p_yln, g_yln);

    // 1) x = LN(src)
    ln_kernel<DD><<<ROWS, 256>>>(src, ln_w, ln_b, p_xln);
    // 2) ur = x @ W_in (16384x512, K=256)
    sgemm2<<<dim3(ROWS/128, DIN_/128), 256>>>(p_xln, W_in, p_ur, nullptr,
                                              ROWS, DIN_, DD);
    // 3) u = gelu(conv3(ur)+b)
    convgelu_k<<<(ROWS*DIN_)/256, 256>>>(conv_w, conv_b);
    // 4) dbc = u @ W_xproj (16384x136, K=512)
    sgemm2<<<dim3(ROWS/128, 2), 256>>>(p_u, W_xproj, p_dbc, nullptr,
                                       ROWS, XPROJ, DIN_);
    // 5) dt/decay
    dtprep_k<<<(ROWS*HH)/256, 256>>>(dt_bias, A_log);
    // 6) scan
    scan_k<<<BB*HH*2, 256>>>(Ds);
    // 7) yln = LN(yc)
    ln_kernel<DIN_><<<ROWS, 256>>>(p_yc, oln_w, oln_b, p_yln);
    // 8) out = src + yln @ W_out (16384x256, K=512)
    sgemm2<<<dim3(ROWS/128, DD/128), 256>>>(p_yln, W_out, out, src,
                                            ROWS, DD, DIN_);
}

// round 8
// speedup vs baseline: 2.0541x; 1.8506x over previous
#include <cuda_runtime.h>
#include <math.h>
#include <stdint.h>

#define BB   8
#define LL   2048
#define DD   256
#define DIN_ 512
#define NN   64
#define PP   64
#define HH   8
#define ROWS (BB*LL)          // 16384
#define XPROJ (HH + 2*NN)     // 136
#define NCH  32               // chunks per sequence
#define CT   64               // chunk length

// ---------------- scratch (device globals) ---------------------------------
__device__ float g_xln[ROWS*DD];
__device__ float g_ur [ROWS*DIN_];
__device__ float g_u  [ROWS*DIN_];
__device__ float g_dbc[ROWS*XPROJ];
__device__ float g_dtd[ROWS*HH*2];      // {dt, dt*A}
__device__ float g_yc [ROWS*DIN_];
__device__ float g_yln[ROWS*DIN_];
__device__ float g_S  [BB*HH*NCH*NN*PP];   // chunk states [bh][c][n][p]
__device__ float g_hin[BB*HH*NCH*NN*PP];   // chunk entry states
__device__ float g_la [BB*HH*NCH*CT];      // log cumulative decay
__device__ float g_pa [BB*HH*NCH];         // exp(la_T) per chunk

// ---------------- helpers ---------------------------------------------------
__device__ __forceinline__ uint32_t smem_u32(const void* p){
    uint32_t a;
    asm("{ .reg .u64 t; cvta.to.shared.u64 t, %1; cvt.u32.u64 %0, t; }" : "=r"(a) : "l"(p));
    return a;
}
__device__ __forceinline__ void cp16(uint32_t dst, const void* src, int sz){
    asm volatile("cp.async.ca.shared.global [%0], [%1], 16, %2;"
                 :: "r"(dst), "l"(src), "r"(sz) : "memory");
}
#define CP_COMMIT() asm volatile("cp.async.commit_group;" ::: "memory")
#define CP_WAIT1()  asm volatile("cp.async.wait_group 1;" ::: "memory")
#define CP_WAIT0()  asm volatile("cp.async.wait_group 0;" ::: "memory")

// ---------------- LayerNorm --------------------------------------------------
template<int W>
__global__ __launch_bounds__(256) void ln_kernel(const float* __restrict__ x,
        const float* __restrict__ w, const float* __restrict__ b,
        float* __restrict__ y)
{
    constexpr int E = W / 256;
    int row = blockIdx.x;
    const float* xr = x + (size_t)row * W;
    float v[E]; float s = 0.f, q = 0.f;
#pragma unroll
    for (int i = 0; i < E; i++) { v[i] = xr[threadIdx.x + 256*i]; s += v[i]; q += v[i]*v[i]; }
#pragma unroll
    for (int o = 16; o; o >>= 1) {
        s += __shfl_xor_sync(0xffffffffu, s, o);
        q += __shfl_xor_sync(0xffffffffu, q, o);
    }
    __shared__ float rs[8], rq[8];
    if ((threadIdx.x & 31) == 0) { rs[threadIdx.x>>5] = s; rq[threadIdx.x>>5] = q; }
    __syncthreads();
    float S = 0.f, Q = 0.f;
#pragma unroll
    for (int i = 0; i < 8; i++) { S += rs[i]; Q += rq[i]; }
    float mean = S / (float)W;
    float rstd = rsqrtf(Q / (float)W - mean*mean + 1e-5f);
    float* yr = y + (size_t)row * W;
#pragma unroll
    for (int i = 0; i < E; i++) {
        int c = threadIdx.x + 256*i;
        yr[c] = (v[i] - mean) * rstd * w[c] + b[c];
    }
}

// ---------------- fp32 SGEMM: 128x128x16, cp.async double buffer ------------
#define ASTRIDE 20
__global__ __launch_bounds__(256) void sgemm2(
    const float* __restrict__ A, const float* __restrict__ B,
    float* __restrict__ C, const float* __restrict__ addend,
    int M, int N, int K)
{
    __shared__ float As[2][128*ASTRIDE];
    __shared__ float Bs[2][16*128];
    const int tid = threadIdx.x;
    const int tx = tid & 15, ty = tid >> 4;
    const int m0 = blockIdx.x * 128, n0 = blockIdx.y * 128;
    const int NC = K >> 4;
    const uint32_t asb = smem_u32(As), bsb = smem_u32(Bs);

    float acc[8][8];
#pragma unroll
    for (int i = 0; i < 8; i++)
#pragma unroll
        for (int j = 0; j < 8; j++) acc[i][j] = 0.f;

    auto issue = [&](int c){
        int s = c & 1;
        int k0 = c << 4;
#pragma unroll
        for (int t = 0; t < 2; t++) {
            int id = tid + t * 256;
            int r = id >> 2, cc = id & 3;
            cp16(asb + s*10240 + r*80 + cc*16,
                 A + (size_t)(m0 + r) * K + k0 + cc*4, 16);
        }
#pragma unroll
        for (int t = 0; t < 2; t++) {
            int id = tid + t * 256;
            int k = id >> 5, n4 = id & 31;
            int n = n0 + n4 * 4;
            int ok = (n + 4 <= N);
            cp16(bsb + s*8192 + k*512 + n4*16,
                 B + (size_t)(k0 + k) * N + (ok ? n : 0), ok ? 16 : 0);
        }
    };

    issue(0); CP_COMMIT();

    for (int c = 0; c < NC; c++) {
        int s = c & 1;
        if (c + 1 < NC) { issue(c + 1); CP_COMMIT(); CP_WAIT1(); }
        else            { CP_WAIT0(); }
        __syncthreads();
        const float* as = As[s];
        const float* bs = Bs[s];
#pragma unroll
        for (int kk = 0; kk < 16; kk++) {
            float a[8], b[8];
#pragma unroll
            for (int i = 0; i < 4; i++) {
                a[i]     = as[(ty*4 + i) * ASTRIDE + kk];
                a[4 + i] = as[(64 + ty*4 + i) * ASTRIDE + kk];
            }
            float4 b0 = *(const float4*)&bs[kk*128 + tx*4];
            float4 b1 = *(const float4*)&bs[kk*128 + 64 + tx*4];
            b[0]=b0.x; b[1]=b0.y; b[2]=b0.z; b[3]=b0.w;
            b[4]=b1.x; b[5]=b1.y; b[6]=b1.z; b[7]=b1.w;
#pragma unroll
            for (int i = 0; i < 8; i++)
#pragma unroll
                for (int j = 0; j < 8; j++)
                    acc[i][j] = fmaf(a[i], b[j], acc[i][j]);
        }
        __syncthreads();
    }

#pragma unroll
    for (int i = 0; i < 8; i++) {
        int m = m0 + ((i < 4) ? (ty*4 + i) : (64 + ty*4 + i - 4));
#pragma unroll
        for (int js = 0; js < 2; js++) {
            int col = n0 + js*64 + tx*4;
            if (col + 4 > N) continue;
            float4 v = make_float4(acc[i][js*4+0], acc[i][js*4+1],
                                   acc[i][js*4+2], acc[i][js*4+3]);
            if (addend) {
                float4 ad = *(const float4*)(addend + (size_t)m * N + col);
                v.x += ad.x; v.y += ad.y; v.z += ad.z; v.w += ad.w;
            }
            *(float4*)(C + (size_t)m * N + col) = v;
        }
    }
}

// ---------------- depthwise conv3 + exact GELU ------------------------------
__global__ __launch_bounds__(256) void convgelu_k(const float* __restrict__ cw,
                                                  const float* __restrict__ cb)
{
    int idx = blockIdx.x * 256 + threadIdx.x;
    if (idx >= ROWS * DIN_) return;
    int c = idx & (DIN_ - 1);
    int l = (idx >> 9) & (LL - 1);
    float w0 = cw[c*3], w1 = cw[c*3+1], w2 = cw[c*3+2];
    float x = g_ur[idx] * w1 + cb[c];
    if (l > 0)      x += g_ur[idx - DIN_] * w0;
    if (l < LL - 1) x += g_ur[idx + DIN_] * w2;
    g_u[idx] = 0.5f * x * (1.f + erff(x * 0.7071067811865476f));
}

// ---------------- dt / dtA prep ---------------------------------------------
__global__ __launch_bounds__(256) void dtprep_k(const float* __restrict__ dt_bias,
                                                const float* __restrict__ A_log)
{
    int i = blockIdx.x * 256 + threadIdx.x;
    if (i >= ROWS * HH) return;
    int h = i & 7;
    int row = i >> 3;
    float xx = g_dbc[(size_t)row * XPROJ + h] + dt_bias[h];
    float dt = (xx > 20.f) ? xx : log1pf(expf(xx));
    g_dtd[2*i]     = dt;
    g_dtd[2*i + 1] = -dt * expf(A_log[h]);   // dt * A (negative)
}

// ---------------- SSD phase A: intra-chunk GEMMs ----------------------------
// grid (NCH, HH, BB), 256 threads, dyn smem 67,328 B.
// NOTE: smem tiles use 65-float row stride -> ALL smem accesses are scalar.
__global__ __launch_bounds__(256,2) void ssdA()
{
    extern __shared__ float sm[];
    float* sB  = sm;            // 64 x 65
    float* sC  = sm + 4160;
    float* sX  = sm + 8320;
    float* sP  = sm + 12480;
    float* sdt = sm + 16640;    // 64
    float* sla = sdt + 64;      // 64
    float* sw  = sla + 64;      // 64
    const int c = blockIdx.x, h = blockIdx.y, b = blockIdx.z;
    const int tid = threadIdx.x;
    const int tx = tid & 15, ty = tid >> 4;
    const size_t r0 = (size_t)b * LL + c * CT;
    const int bh = b * HH + h;

#pragma unroll
    for (int i = 0; i < 4; i++) {
        int row = i * 16 + ty;
        const float* dr = g_dbc + (r0 + row) * XPROJ;
        float4 bv = *(const float4*)(dr + 8  + tx*4);
        float4 cv = *(const float4*)(dr + 72 + tx*4);
        float4 xv = *(const float4*)(g_u + (r0 + row)*DIN_ + h*64 + tx*4);
        sB[row*65 + tx*4+0]=bv.x; sB[row*65 + tx*4+1]=bv.y;
        sB[row*65 + tx*4+2]=bv.z; sB[row*65 + tx*4+3]=bv.w;
        sC[row*65 + tx*4+0]=cv.x; sC[row*65 + tx*4+1]=cv.y;
        sC[row*65 + tx*4+2]=cv.z; sC[row*65 + tx*4+3]=cv.w;
        sX[row*65 + tx*4+0]=xv.x; sX[row*65 + tx*4+1]=xv.y;
        sX[row*65 + tx*4+2]=xv.z; sX[row*65 + tx*4+3]=xv.w;
    }
    if (tid < 64) {
        float2 dd = *(const float2*)(g_dtd + ((r0 + tid)*HH + h)*2);
        sdt[tid] = dd.x;
        sla[tid] = dd.y;
    }
    __syncthreads();
    // inclusive scan of log-decay
#pragma unroll
    for (int off = 1; off < 64; off <<= 1) {
        float v = 0.f;
        if (tid >= off && tid < 64) v = sla[tid - off];
        __syncthreads();
        if (tid < 64) sla[tid] += v;
        __syncthreads();
    }
    if (tid < 64) sw[tid] = sdt[tid] * __expf(sla[63] - sla[tid]);
    __syncthreads();

    // GEMM1: P[t][s] = C_t . B_s  -> masked/decayed
    float acc[4][4];
#pragma unroll
    for (int i=0;i<4;i++)
#pragma unroll
        for (int j=0;j<4;j++) acc[i][j]=0.f;
#pragma unroll 8
    for (int n = 0; n < 64; n++) {
        float a[4], bb[4];
#pragma unroll
        for (int i=0;i<4;i++) a[i]  = sC[(ty*4+i)*65 + n];
#pragma unroll
        for (int j=0;j<4;j++) bb[j] = sB[(tx*4+j)*65 + n];
#pragma unroll
        for (int i=0;i<4;i++)
#pragma unroll
            for (int j=0;j<4;j++) acc[i][j] = fmaf(a[i], bb[j], acc[i][j]);
    }
#pragma unroll
    for (int i=0;i<4;i++) {
        int t = ty*4 + i;
#pragma unroll
        for (int j=0;j<4;j++) {
            int s = tx*4 + j;
            sP[t*65 + s] = (s <= t) ? acc[i][j] * __expf(sla[t] - sla[s]) * sdt[s] : 0.f;
        }
    }
    __syncthreads();

    // GEMM2: y1[t][p] = P @ x
#pragma unroll
    for (int i=0;i<4;i++)
#pragma unroll
        for (int j=0;j<4;j++) acc[i][j]=0.f;
#pragma unroll 8
    for (int s = 0; s < 64; s++) {
        float a[4], bb[4];
#pragma unroll
        for (int i=0;i<4;i++) a[i]  = sP[(ty*4+i)*65 + s];
#pragma unroll
        for (int j=0;j<4;j++) bb[j] = sX[s*65 + tx*4 + j];
#pragma unroll
        for (int i=0;i<4;i++)
#pragma unroll
            for (int j=0;j<4;j++) acc[i][j] = fmaf(a[i], bb[j], acc[i][j]);
    }
#pragma unroll
    for (int i=0;i<4;i++) {
        int t = ty*4 + i;
        *(float4*)(g_yc + (r0 + t)*DIN_ + h*64 + tx*4) =
            make_float4(acc[i][0], acc[i][1], acc[i][2], acc[i][3]);
    }
    __syncthreads();

    // overwrite sP with weighted x: Xw[s][p] = w_s * x[s][p]
#pragma unroll
    for (int i = 0; i < 4; i++) {
        int row = i * 16 + ty;
        float wv = sw[row];
#pragma unroll
        for (int j = 0; j < 4; j++)
            sP[row*65 + tx*4 + j] = wv * sX[row*65 + tx*4 + j];
    }
    __syncthreads();

    // GEMM3: S[n][p] = sum_s B[s][n] * Xw[s][p]
#pragma unroll
    for (int i=0;i<4;i++)
#pragma unroll
        for (int j=0;j<4;j++) acc[i][j]=0.f;
#pragma unroll 8
    for (int s = 0; s < 64; s++) {
        float a[4], bb[4];
#pragma unroll
        for (int i=0;i<4;i++) a[i]  = sB[s*65 + ty*4 + i];
#pragma unroll
        for (int j=0;j<4;j++) bb[j] = sP[s*65 + tx*4 + j];
#pragma unroll
        for (int i=0;i<4;i++)
#pragma unroll
            for (int j=0;j<4;j++) acc[i][j] = fmaf(a[i], bb[j], acc[i][j]);
    }
    size_t so = ((size_t)bh * NCH + c) * (NN*PP);
#pragma unroll
    for (int i=0;i<4;i++) {
        int n = ty*4 + i;
        *(float4*)(g_S + so + n*64 + tx*4) =
            make_float4(acc[i][0], acc[i][1], acc[i][2], acc[i][3]);
    }
    if (tid < 64) g_la[((size_t)bh*NCH + c)*CT + tid] = sla[tid];
    if (tid == 0) g_pa[bh*NCH + c] = __expf(sla[63]);
}

// ---------------- SSD phase B: sequential chunk combine ---------------------
__global__ __launch_bounds__(256) void ssdB()
{
    int bh = blockIdx.x, tid = threadIdx.x;
    float h[16];
#pragma unroll
    for (int i=0;i<16;i++) h[i]=0.f;
    size_t base = (size_t)bh * NCH * (NN*PP);
    for (int c = 0; c < NCH; c++) {
        float pa = g_pa[bh*NCH + c];
        size_t cb = base + (size_t)c * (NN*PP);
#pragma unroll
        for (int i=0;i<16;i++) {
            size_t idx = cb + i*256 + tid;
            g_hin[idx] = h[i];
            h[i] = h[i]*pa + g_S[idx];
        }
    }
}

// ---------------- SSD phase C: state broadcast + epilogue -------------------
// y = y1 + exp(la_t) C @ h_in + Ds * x  (scalar smem accesses, 65 stride)
__global__ __launch_bounds__(256,2) void ssdC(const float* __restrict__ Ds)
{
    __shared__ float sCl[64*65];
    __shared__ float sH [64*65];
    __shared__ float sla2[64];
    const int c = blockIdx.x, h = blockIdx.y, b = blockIdx.z;
    const int tid = threadIdx.x;
    const int tx = tid & 15, ty = tid >> 4;
    const size_t r0 = (size_t)b * LL + c * CT;
    const int bh = b * HH + h;

    if (tid < 64) sla2[tid] = g_la[((size_t)bh*NCH + c)*CT + tid];
    __syncthreads();
#pragma unroll
    for (int i = 0; i < 4; i++) {
        int row = i * 16 + ty;
        float4 cv = *(const float4*)(g_dbc + (r0 + row)*XPROJ + 72 + tx*4);
        float e = __expf(sla2[row]);
        float4 hv = *(const float4*)(g_hin + ((size_t)bh*NCH + c)*(NN*PP) + row*64 + tx*4);
        sCl[row*65 + tx*4+0] = cv.x*e; sCl[row*65 + tx*4+1] = cv.y*e;
        sCl[row*65 + tx*4+2] = cv.z*e; sCl[row*65 + tx*4+3] = cv.w*e;
        sH [row*65 + tx*4+0] = hv.x;   sH [row*65 + tx*4+1] = hv.y;
        sH [row*65 + tx*4+2] = hv.z;   sH [row*65 + tx*4+3] = hv.w;
    }
    __syncthreads();

    float acc[4][4];
#pragma unroll
    for (int i=0;i<4;i++)
#pragma unroll
        for (int j=0;j<4;j++) acc[i][j]=0.f;
#pragma unroll 8
    for (int n = 0; n < 64; n++) {
        float a[4], bb[4];
#pragma unroll
        for (int i=0;i<4;i++) a[i]  = sCl[(ty*4+i)*65 + n];
#pragma unroll
        for (int j=0;j<4;j++) bb[j] = sH[n*65 + tx*4 + j];
#pragma unroll
        for (int i=0;i<4;i++)
#pragma unroll
            for (int j=0;j<4;j++) acc[i][j] = fmaf(a[i], bb[j], acc[i][j]);
    }
    float dsh = Ds[h];
#pragma unroll
    for (int i=0;i<4;i++) {
        int t = ty*4 + i;
        float* yp = g_yc + (r0 + t)*DIN_ + h*64 + tx*4;
        float4 y1 = *(float4*)yp;
        float4 xv = *(const float4*)(g_u + (r0 + t)*DIN_ + h*64 + tx*4);
        y1.x += acc[i][0] + dsh*xv.x;
        y1.y += acc[i][1] + dsh*xv.y;
        y1.z += acc[i][2] + dsh*xv.z;
        y1.w += acc[i][3] + dsh*xv.w;
        *(float4*)yp = y1;
    }
}

// ---------------- launch ----------------------------------------------------
extern "C" void kernel_launch(void* const* d_in, const int* in_sizes, int n_in,
                              void* d_out, int out_size)
{
    const float* src     = (const float*)d_in[0];
    const float* ln_w    = (const float*)d_in[1];
    const float* ln_b    = (const float*)d_in[2];
    const float* W_in    = (const float*)d_in[3];
    const float* conv_w  = (const float*)d_in[4];
    const float* conv_b  = (const float*)d_in[5];
    const float* W_xproj = (const float*)d_in[6];
    const float* dt_bias = (const float*)d_in[7];
    const float* A_log   = (const float*)d_in[8];
    const float* Ds      = (const float*)d_in[9];
    const float* oln_w   = (const float*)d_in[10];
    const float* oln_b   = (const float*)d_in[11];
    const float* W_out   = (const float*)d_in[12];
    float* out = (float*)d_out;

    float *p_xln, *p_ur, *p_u, *p_dbc, *p_yc, *p_yln;
    cudaGetSymbolAddress((void**)&p_xln, g_xln);
    cudaGetSymbolAddress((void**)&p_ur,  g_ur);
    cudaGetSymbolAddress((void**)&p_u,   g_u);
    cudaGetSymbolAddress((void**)&p_dbc, g_dbc);
    cudaGetSymbolAddress((void**)&p_yc,  g_yc);
    cudaGetSymbolAddress((void**)&p_yln, g_yln);

    const int ASMEM = 67328;
    cudaFuncSetAttribute(ssdA, cudaFuncAttributeMaxDynamicSharedMemorySize, ASMEM);

    // 1) x = LN(src)
    ln_kernel<DD><<<ROWS, 256>>>(src, ln_w, ln_b, p_xln);
    // 2) ur = x @ W_in
    sgemm2<<<dim3(ROWS/128, DIN_/128), 256>>>(p_xln, W_in, p_ur, nullptr,
                                              ROWS, DIN_, DD);
    // 3) u = gelu(conv3(ur)+b)
    convgelu_k<<<(ROWS*DIN_)/256, 256>>>(conv_w, conv_b);
    // 4) dbc = u @ W_xproj
    sgemm2<<<dim3(ROWS/128, 2), 256>>>(p_u, W_xproj, p_dbc, nullptr,
                                       ROWS, XPROJ, DIN_);
    // 5) dt / dtA
    dtprep_k<<<(ROWS*HH)/256, 256>>>(dt_bias, A_log);
    // 6) chunked scan: A (parallel) -> B (tiny sequential) -> C (parallel)
    ssdA<<<dim3(NCH, HH, BB), 256, ASMEM>>>();
    ssdB<<<BB*HH, 256>>>();
    ssdC<<<dim3(NCH, HH, BB), 256>>>(Ds);
    // 7) yln = LN(yc)
    ln_kernel<DIN_><<<ROWS, 256>>>(p_yc, oln_w, oln_b, p_yln);
    // 8) out = src + yln @ W_out
    sgemm2<<<dim3(ROWS/128, DD/128), 256>>>(p_yln, W_out, out, src,
                                            ROWS, DD, DIN_);
}

// round 9
// speedup vs baseline: 2.1412x; 1.0424x over previous
#include <cuda_runtime.h>
#include <math.h>
#include <stdint.h>

#define BB   8
#define LL   2048
#define DD   256
#define DIN_ 512
#define NN   64
#define PP   64
#define HH   8
#define ROWS (BB*LL)          // 16384
#define XPROJ (HH + 2*NN)     // 136
#define NCH  32               // chunks per sequence
#define CT   64               // chunk length

// ---------------- scratch (device globals) ---------------------------------
__device__ float g_xln[ROWS*DD];
__device__ float g_ur [ROWS*DIN_];
__device__ float g_u  [ROWS*DIN_];
__device__ float g_dbc[ROWS*XPROJ];
__device__ float g_yc [ROWS*DIN_];
__device__ float g_yln[ROWS*DIN_];
__device__ float g_S  [BB*HH*NCH*NN*PP];   // chunk states [bh][c][n][p]
__device__ float g_hin[BB*HH*NCH*NN*PP];   // chunk entry states
__device__ float g_la [BB*HH*NCH*CT];      // log cumulative decay
__device__ float g_pa [BB*HH*NCH];         // exp(la_T) per chunk

// ---------------- helpers ---------------------------------------------------
__device__ __forceinline__ uint32_t smem_u32(const void* p){
    uint32_t a;
    asm("{ .reg .u64 t; cvta.to.shared.u64 t, %1; cvt.u32.u64 %0, t; }" : "=r"(a) : "l"(p));
    return a;
}
__device__ __forceinline__ void cp16(uint32_t dst, const void* src, int sz){
    asm volatile("cp.async.ca.shared.global [%0], [%1], 16, %2;"
                 :: "r"(dst), "l"(src), "r"(sz) : "memory");
}
#define CP_COMMIT() asm volatile("cp.async.commit_group;" ::: "memory")
#define CP_WAIT1()  asm volatile("cp.async.wait_group 1;" ::: "memory")
#define CP_WAIT0()  asm volatile("cp.async.wait_group 0;" ::: "memory")

// ---------------- LayerNorm --------------------------------------------------
template<int W>
__global__ __launch_bounds__(256) void ln_kernel(const float* __restrict__ x,
        const float* __restrict__ w, const float* __restrict__ b,
        float* __restrict__ y)
{
    constexpr int E = W / 256;
    int row = blockIdx.x;
    const float* xr = x + (size_t)row * W;
    float v[E]; float s = 0.f, q = 0.f;
#pragma unroll
    for (int i = 0; i < E; i++) { v[i] = xr[threadIdx.x + 256*i]; s += v[i]; q += v[i]*v[i]; }
#pragma unroll
    for (int o = 16; o; o >>= 1) {
        s += __shfl_xor_sync(0xffffffffu, s, o);
        q += __shfl_xor_sync(0xffffffffu, q, o);
    }
    __shared__ float rs[8], rq[8];
    if ((threadIdx.x & 31) == 0) { rs[threadIdx.x>>5] = s; rq[threadIdx.x>>5] = q; }
    __syncthreads();
    float S = 0.f, Q = 0.f;
#pragma unroll
    for (int i = 0; i < 8; i++) { S += rs[i]; Q += rq[i]; }
    float mean = S / (float)W;
    float rstd = rsqrtf(Q / (float)W - mean*mean + 1e-5f);
    float* yr = y + (size_t)row * W;
#pragma unroll
    for (int i = 0; i < E; i++) {
        int c = threadIdx.x + 256*i;
        yr[c] = (v[i] - mean) * rstd * w[c] + b[c];
    }
}

// ---------------- fp32 SGEMM: 128x128x32, cp.async double buffer ------------
#define AST 36                  // A smem row stride (floats)
#define GSMEM ((2*128*AST + 2*32*128) * 4)   // 69632 bytes
__global__ __launch_bounds__(256) void sgemm2(
    const float* __restrict__ A, const float* __restrict__ B,
    float* __restrict__ C, const float* __restrict__ addend,
    int M, int N, int K)
{
    extern __shared__ float dsm[];
    float* As = dsm;                       // 2 x 128 x AST
    float* Bs = dsm + 2*128*AST;           // 2 x 32 x 128
    const int tid = threadIdx.x;
    const int tx = tid & 15, ty = tid >> 4;
    const int m0 = blockIdx.x * 128, n0 = blockIdx.y * 128;
    const int NC = K >> 5;
    const uint32_t asb = smem_u32(As), bsb = smem_u32(Bs);

    float acc[8][8];
#pragma unroll
    for (int i = 0; i < 8; i++)
#pragma unroll
        for (int j = 0; j < 8; j++) acc[i][j] = 0.f;

    auto issue = [&](int c){
        int s = c & 1;
        int k0 = c << 5;
#pragma unroll
        for (int t = 0; t < 4; t++) {
            int id = tid + t * 256;
            int r = id >> 3, cc = id & 7;
            cp16(asb + s*18432 + r*144 + cc*16,
                 A + (size_t)(m0 + r) * K + k0 + cc*4, 16);
        }
#pragma unroll
        for (int t = 0; t < 4; t++) {
            int id = tid + t * 256;
            int k = id >> 5, n4 = id & 31;
            int n = n0 + n4 * 4;
            int ok = (n + 4 <= N);
            cp16(bsb + s*16384 + k*512 + n4*16,
                 B + (size_t)(k0 + k) * N + (ok ? n : 0), ok ? 16 : 0);
        }
    };

    issue(0); CP_COMMIT();

    for (int c = 0; c < NC; c++) {
        int s = c & 1;
        if (c + 1 < NC) { issue(c + 1); CP_COMMIT(); CP_WAIT1(); }
        else            { CP_WAIT0(); }
        __syncthreads();
        const float* as = As + s * (128*AST);
        const float* bs = Bs + s * (32*128);
#pragma unroll
        for (int kk = 0; kk < 32; kk++) {
            float a[8], b[8];
#pragma unroll
            for (int i = 0; i < 4; i++) {
                a[i]     = as[(ty*4 + i) * AST + kk];
                a[4 + i] = as[(64 + ty*4 + i) * AST + kk];
            }
            float4 b0 = *(const float4*)&bs[kk*128 + tx*4];
            float4 b1 = *(const float4*)&bs[kk*128 + 64 + tx*4];
            b[0]=b0.x; b[1]=b0.y; b[2]=b0.z; b[3]=b0.w;
            b[4]=b1.x; b[5]=b1.y; b[6]=b1.z; b[7]=b1.w;
#pragma unroll
            for (int i = 0; i < 8; i++)
#pragma unroll
                for (int j = 0; j < 8; j++)
                    acc[i][j] = fmaf(a[i], b[j], acc[i][j]);
        }
        __syncthreads();
    }

#pragma unroll
    for (int i = 0; i < 8; i++) {
        int m = m0 + ((i < 4) ? (ty*4 + i) : (64 + ty*4 + i - 4));
#pragma unroll
        for (int js = 0; js < 2; js++) {
            int col = n0 + js*64 + tx*4;
            if (col + 4 > N) continue;
            float4 v = make_float4(acc[i][js*4+0], acc[i][js*4+1],
                                   acc[i][js*4+2], acc[i][js*4+3]);
            if (addend) {
                float4 ad = *(const float4*)(addend + (size_t)m * N + col);
                v.x += ad.x; v.y += ad.y; v.z += ad.z; v.w += ad.w;
            }
            *(float4*)(C + (size_t)m * N + col) = v;
        }
    }
}

// ---------------- skinny GEMM: dbc cols 128..135 (last 8 C cols) ------------
// grid 2048 x 256 threads (8 warps, 1 row each). W cached in smem (stride 9).
__global__ __launch_bounds__(256) void skinny8(const float* __restrict__ Wx)
{
    __shared__ float sW[512*9];
    const int tid = threadIdx.x;
#pragma unroll
    for (int t = 0; t < 16; t++) {
        int idx = tid + t * 256;
        int k = idx >> 3, c = idx & 7;
        sW[k*9 + c] = Wx[(size_t)k * XPROJ + 128 + c];
    }
    __syncthreads();
    int row = blockIdx.x * 8 + (tid >> 5);
    int lane = tid & 31;
    float acc[8];
#pragma unroll
    for (int c = 0; c < 8; c++) acc[c] = 0.f;
    const float* ur = g_u + (size_t)row * DIN_;
#pragma unroll
    for (int i = 0; i < 16; i++) {
        int k = lane + i * 32;
        float uv = ur[k];
#pragma unroll
        for (int c = 0; c < 8; c++)
            acc[c] = fmaf(uv, sW[k*9 + c], acc[c]);
    }
#pragma unroll
    for (int o = 16; o; o >>= 1)
#pragma unroll
        for (int c = 0; c < 8; c++)
            acc[c] += __shfl_xor_sync(0xffffffffu, acc[c], o);
    if (lane == 0) {
#pragma unroll
        for (int c = 0; c < 8; c++)
            g_dbc[(size_t)row * XPROJ + 128 + c] = acc[c];
    }
}

// ---------------- depthwise conv3 + exact GELU ------------------------------
__global__ __launch_bounds__(256) void convgelu_k(const float* __restrict__ cw,
                                                  const float* __restrict__ cb)
{
    int idx = blockIdx.x * 256 + threadIdx.x;
    if (idx >= ROWS * DIN_) return;
    int c = idx & (DIN_ - 1);
    int l = (idx >> 9) & (LL - 1);
    float w0 = cw[c*3], w1 = cw[c*3+1], w2 = cw[c*3+2];
    float x = g_ur[idx] * w1 + cb[c];
    if (l > 0)      x += g_ur[idx - DIN_] * w0;
    if (l < LL - 1) x += g_ur[idx + DIN_] * w2;
    g_u[idx] = 0.5f * x * (1.f + erff(x * 0.7071067811865476f));
}

// ---------------- SSD phase A: fused dt prep + intra-chunk GEMMs ------------
// grid (NCH, HH, BB), 256 threads, dyn smem 67,328 B. Scalar smem accesses.
__global__ __launch_bounds__(256,2) void ssdA(const float* __restrict__ dt_bias,
                                              const float* __restrict__ A_log)
{
    extern __shared__ float sm[];
    float* sB  = sm;            // 64 x 65
    float* sC  = sm + 4160;
    float* sX  = sm + 8320;
    float* sP  = sm + 12480;
    float* sdt = sm + 16640;    // 64
    float* sla = sdt + 64;      // 64
    float* sw  = sla + 64;      // 64
    const int c = blockIdx.x, h = blockIdx.y, b = blockIdx.z;
    const int tid = threadIdx.x;
    const int tx = tid & 15, ty = tid >> 4;
    const size_t r0 = (size_t)b * LL + c * CT;
    const int bh = b * HH + h;

#pragma unroll
    for (int i = 0; i < 4; i++) {
        int row = i * 16 + ty;
        const float* dr = g_dbc + (r0 + row) * XPROJ;
        float4 bv = *(const float4*)(dr + 8  + tx*4);
        float4 cv = *(const float4*)(dr + 72 + tx*4);
        float4 xv = *(const float4*)(g_u + (r0 + row)*DIN_ + h*64 + tx*4);
        sB[row*65 + tx*4+0]=bv.x; sB[row*65 + tx*4+1]=bv.y;
        sB[row*65 + tx*4+2]=bv.z; sB[row*65 + tx*4+3]=bv.w;
        sC[row*65 + tx*4+0]=cv.x; sC[row*65 + tx*4+1]=cv.y;
        sC[row*65 + tx*4+2]=cv.z; sC[row*65 + tx*4+3]=cv.w;
        sX[row*65 + tx*4+0]=xv.x; sX[row*65 + tx*4+1]=xv.y;
        sX[row*65 + tx*4+2]=xv.z; sX[row*65 + tx*4+3]=xv.w;
    }
    // fused dt prep + warp-level inclusive scan of log-decay
    if (tid < 64) {
        float xx = g_dbc[(r0 + tid)*XPROJ + h] + dt_bias[h];
        float dt = (xx > 20.f) ? xx : log1pf(expf(xx));
        float la = -dt * expf(A_log[h]);
        int lane = tid & 31;
        float v = la;
#pragma unroll
        for (int o = 1; o < 32; o <<= 1) {
            float pv = __shfl_up_sync(0xffffffffu, v, o);
            if (lane >= o) v += pv;
        }
        sdt[tid] = dt;
        sla[tid] = v;
    }
    __syncthreads();
    if (tid >= 32 && tid < 64) sla[tid] += sla[31];
    __syncthreads();
    if (tid < 64) sw[tid] = sdt[tid] * __expf(sla[63] - sla[tid]);
    __syncthreads();

    // GEMM1: P[t][s] = C_t . B_s  -> masked/decayed
    float acc[4][4];
#pragma unroll
    for (int i=0;i<4;i++)
#pragma unroll
        for (int j=0;j<4;j++) acc[i][j]=0.f;
#pragma unroll 8
    for (int n = 0; n < 64; n++) {
        float a[4], bb[4];
#pragma unroll
        for (int i=0;i<4;i++) a[i]  = sC[(ty*4+i)*65 + n];
#pragma unroll
        for (int j=0;j<4;j++) bb[j] = sB[(tx*4+j)*65 + n];
#pragma unroll
        for (int i=0;i<4;i++)
#pragma unroll
            for (int j=0;j<4;j++) acc[i][j] = fmaf(a[i], bb[j], acc[i][j]);
    }
#pragma unroll
    for (int i=0;i<4;i++) {
        int t = ty*4 + i;
#pragma unroll
        for (int j=0;j<4;j++) {
            int s = tx*4 + j;
            sP[t*65 + s] = (s <= t) ? acc[i][j] * __expf(sla[t] - sla[s]) * sdt[s] : 0.f;
        }
    }
    __syncthreads();

    // GEMM2: y1[t][p] = P @ x
#pragma unroll
    for (int i=0;i<4;i++)
#pragma unroll
        for (int j=0;j<4;j++) acc[i][j]=0.f;
#pragma unroll 8
    for (int s = 0; s < 64; s++) {
        float a[4], bb[4];
#pragma unroll
        for (int i=0;i<4;i++) a[i]  = sP[(ty*4+i)*65 + s];
#pragma unroll
        for (int j=0;j<4;j++) bb[j] = sX[s*65 + tx*4 + j];
#pragma unroll
        for (int i=0;i<4;i++)
#pragma unroll
            for (int j=0;j<4;j++) acc[i][j] = fmaf(a[i], bb[j], acc[i][j]);
    }
#pragma unroll
    for (int i=0;i<4;i++) {
        int t = ty*4 + i;
        *(float4*)(g_yc + (r0 + t)*DIN_ + h*64 + tx*4) =
            make_float4(acc[i][0], acc[i][1], acc[i][2], acc[i][3]);
    }
    __syncthreads();

    // overwrite sP with weighted x: Xw[s][p] = w_s * x[s][p]
#pragma unroll
    for (int i = 0; i < 4; i++) {
        int row = i * 16 + ty;
        float wv = sw[row];
#pragma unroll
        for (int j = 0; j < 4; j++)
            sP[row*65 + tx*4 + j] = wv * sX[row*65 + tx*4 + j];
    }
    __syncthreads();

    // GEMM3: S[n][p] = sum_s B[s][n] * Xw[s][p]
#pragma unroll
    for (int i=0;i<4;i++)
#pragma unroll
        for (int j=0;j<4;j++) acc[i][j]=0.f;
#pragma unroll 8
    for (int s = 0; s < 64; s++) {
        float a[4], bb[4];
#pragma unroll
        for (int i=0;i<4;i++) a[i]  = sB[s*65 + ty*4 + i];
#pragma unroll
        for (int j=0;j<4;j++) bb[j] = sP[s*65 + tx*4 + j];
#pragma unroll
        for (int i=0;i<4;i++)
#pragma unroll
            for (int j=0;j<4;j++) acc[i][j] = fmaf(a[i], bb[j], acc[i][j]);
    }
    size_t so = ((size_t)bh * NCH + c) * (NN*PP);
#pragma unroll
    for (int i=0;i<4;i++) {
        int n = ty*4 + i;
        *(float4*)(g_S + so + n*64 + tx*4) =
            make_float4(acc[i][0], acc[i][1], acc[i][2], acc[i][3]);
    }
    if (tid < 64) g_la[((size_t)bh*NCH + c)*CT + tid] = sla[tid];
    if (tid == 0) g_pa[bh*NCH + c] = __expf(sla[63]);
}

// ---------------- SSD phase B: sequential chunk combine ---------------------
__global__ __launch_bounds__(256) void ssdB()
{
    int bh = blockIdx.x, tid = threadIdx.x;
    float h[16];
#pragma unroll
    for (int i=0;i<16;i++) h[i]=0.f;
    size_t base = (size_t)bh * NCH * (NN*PP);
    for (int c = 0; c < NCH; c++) {
        float pa = g_pa[bh*NCH + c];
        size_t cb = base + (size_t)c * (NN*PP);
#pragma unroll
        for (int i=0;i<16;i++) {
            size_t idx = cb + i*256 + tid;
            g_hin[idx] = h[i];
            h[i] = h[i]*pa + g_S[idx];
        }
    }
}

// ---------------- SSD phase C: state broadcast + epilogue -------------------
__global__ __launch_bounds__(256,2) void ssdC(const float* __restrict__ Ds)
{
    __shared__ float sCl[64*65];
    __shared__ float sH [64*65];
    __shared__ float sla2[64];
    const int c = blockIdx.x, h = blockIdx.y, b = blockIdx.z;
    const int tid = threadIdx.x;
    const int tx = tid & 15, ty = tid >> 4;
    const size_t r0 = (size_t)b * LL + c * CT;
    const int bh = b * HH + h;

    if (tid < 64) sla2[tid] = g_la[((size_t)bh*NCH + c)*CT + tid];
    __syncthreads();
#pragma unroll
    for (int i = 0; i < 4; i++) {
        int row = i * 16 + ty;
        float4 cv = *(const float4*)(g_dbc + (r0 + row)*XPROJ + 72 + tx*4);
        float e = __expf(sla2[row]);
        float4 hv = *(const float4*)(g_hin + ((size_t)bh*NCH + c)*(NN*PP) + row*64 + tx*4);
        sCl[row*65 + tx*4+0] = cv.x*e; sCl[row*65 + tx*4+1] = cv.y*e;
        sCl[row*65 + tx*4+2] = cv.z*e; sCl[row*65 + tx*4+3] = cv.w*e;
        sH [row*65 + tx*4+0] = hv.x;   sH [row*65 + tx*4+1] = hv.y;
        sH [row*65 + tx*4+2] = hv.z;   sH [row*65 + tx*4+3] = hv.w;
    }
    __syncthreads();

    float acc[4][4];
#pragma unroll
    for (int i=0;i<4;i++)
#pragma unroll
        for (int j=0;j<4;j++) acc[i][j]=0.f;
#pragma unroll 8
    for (int n = 0; n < 64; n++) {
        float a[4], bb[4];
#pragma unroll
        for (int i=0;i<4;i++) a[i]  = sCl[(ty*4+i)*65 + n];
#pragma unroll
        for (int j=0;j<4;j++) bb[j] = sH[n*65 + tx*4 + j];
#pragma unroll
        for (int i=0;i<4;i++)
#pragma unroll
            for (int j=0;j<4;j++) acc[i][j] = fmaf(a[i], bb[j], acc[i][j]);
    }
    float dsh = Ds[h];
#pragma unroll
    for (int i=0;i<4;i++) {
        int t = ty*4 + i;
        float* yp = g_yc + (r0 + t)*DIN_ + h*64 + tx*4;
        float4 y1 = *(float4*)yp;
        float4 xv = *(const float4*)(g_u + (r0 + t)*DIN_ + h*64 + tx*4);
        y1.x += acc[i][0] + dsh*xv.x;
        y1.y += acc[i][1] + dsh*xv.y;
        y1.z += acc[i][2] + dsh*xv.z;
        y1.w += acc[i][3] + dsh*xv.w;
        *(float4*)yp = y1;
    }
}

// ---------------- launch ----------------------------------------------------
extern "C" void kernel_launch(void* const* d_in, const int* in_sizes, int n_in,
                              void* d_out, int out_size)
{
    const float* src     = (const float*)d_in[0];
    const float* ln_w    = (const float*)d_in[1];
    const float* ln_b    = (const float*)d_in[2];
    const float* W_in    = (const float*)d_in[3];
    const float* conv_w  = (const float*)d_in[4];
    const float* conv_b  = (const float*)d_in[5];
    const float* W_xproj = (const float*)d_in[6];
    const float* dt_bias = (const float*)d_in[7];
    const float* A_log   = (const float*)d_in[8];
    const float* Ds      = (const float*)d_in[9];
    const float* oln_w   = (const float*)d_in[10];
    const float* oln_b   = (const float*)d_in[11];
    const float* W_out   = (const float*)d_in[12];
    float* out = (float*)d_out;

    float *p_xln, *p_ur, *p_u, *p_dbc, *p_yc, *p_yln;
    cudaGetSymbolAddress((void**)&p_xln, g_xln);
    cudaGetSymbolAddress((void**)&p_ur,  g_ur);
    cudaGetSymbolAddress((void**)&p_u,   g_u);
    cudaGetSymbolAddress((void**)&p_dbc, g_dbc);
    cudaGetSymbolAddress((void**)&p_yc,  g_yc);
    cudaGetSymbolAddress((void**)&p_yln, g_yln);

    const int ASMEM = 67328;
    cudaFuncSetAttribute(ssdA, cudaFuncAttributeMaxDynamicSharedMemorySize, ASMEM);
    cudaFuncSetAttribute(sgemm2, cudaFuncAttributeMaxDynamicSharedMemorySize, GSMEM);

    // 1) x = LN(src)
    ln_kernel<DD><<<ROWS, 256>>>(src, ln_w, ln_b, p_xln);
    // 2) ur = x @ W_in
    sgemm2<<<dim3(ROWS/128, DIN_/128), 256, GSMEM>>>(p_xln, W_in, p_ur, nullptr,
                                                     ROWS, DIN_, DD);
    // 3) u = gelu(conv3(ur)+b)
    convgelu_k<<<(ROWS*DIN_)/256, 256>>>(conv_w, conv_b);
    // 4) dbc = u @ W_xproj: 128-col main tile + skinny last 8 cols
    sgemm2<<<dim3(ROWS/128, 1), 256, GSMEM>>>(p_u, W_xproj, p_dbc, nullptr,
                                              ROWS, XPROJ, DIN_);
    skinny8<<<ROWS/8, 256>>>(W_xproj);
    // 5) chunked scan: A (parallel, fused dt) -> B (tiny sequential) -> C
    ssdA<<<dim3(NCH, HH, BB), 256, ASMEM>>>(dt_bias, A_log);
    ssdB<<<BB*HH, 256>>>();
    ssdC<<<dim3(NCH, HH, BB), 256>>>(Ds);
    // 6) yln = LN(yc)
    ln_kernel<DIN_><<<ROWS, 256>>>(p_yc, oln_w, oln_b, p_yln);
    // 7) out = src + yln @ W_out
    sgemm2<<<dim3(ROWS/128, DD/128), 256, GSMEM>>>(p_yln, W_out, out, src,
                                                   ROWS, DD, DIN_);
}

// round 10
// speedup vs baseline: 2.2111x; 1.0327x over previous
#include <cuda_runtime.h>
#include <math.h>
#include <stdint.h>

#define BB   8
#define LL   2048
#define DD   256
#define DIN_ 512
#define NN   64
#define PP   64
#define HH   8
#define ROWS (BB*LL)          // 16384
#define XPROJ (HH + 2*NN)     // 136
#define NCH  32               // chunks per sequence
#define CT   64               // chunk length

typedef unsigned long long u64;

// ---------------- scratch (device globals) ---------------------------------
__device__ float g_xln[ROWS*DD];
__device__ float g_ur [ROWS*DIN_];
__device__ float g_u  [ROWS*DIN_];
__device__ float g_dbc[ROWS*XPROJ];
__device__ float g_yc [ROWS*DIN_];
__device__ float g_yln[ROWS*DIN_];
__device__ float g_S  [BB*HH*NCH*NN*PP];
__device__ float g_hin[BB*HH*NCH*NN*PP];
__device__ float g_la [BB*HH*NCH*CT];
__device__ float g_pa [BB*HH*NCH];

// ---------------- helpers ---------------------------------------------------
__device__ __forceinline__ uint32_t smem_u32(const void* p){
    uint32_t a;
    asm("{ .reg .u64 t; cvta.to.shared.u64 t, %1; cvt.u32.u64 %0, t; }" : "=r"(a) : "l"(p));
    return a;
}
__device__ __forceinline__ void cp16(uint32_t dst, const void* src, int sz){
    asm volatile("cp.async.ca.shared.global [%0], [%1], 16, %2;"
                 :: "r"(dst), "l"(src), "r"(sz) : "memory");
}
#define CP_COMMIT() asm volatile("cp.async.commit_group;" ::: "memory")
#define CP_WAIT1()  asm volatile("cp.async.wait_group 1;" ::: "memory")
#define CP_WAIT0()  asm volatile("cp.async.wait_group 0;" ::: "memory")

// packed f32x2
#define PK2(d, lo, hi) asm("mov.b64 %0, {%1,%2};" : "=l"(d) : "r"(__float_as_uint(lo)), "r"(__float_as_uint(hi)))
#define DUP2(d, x)     asm("mov.b64 %0, {%1,%1};" : "=l"(d) : "r"(__float_as_uint(x)))
#define UPK2(lo, hi, v) do { uint32_t _a,_b; asm("mov.b64 {%0,%1}, %2;" : "=r"(_a), "=r"(_b) : "l"(v)); lo=__uint_as_float(_a); hi=__uint_as_float(_b); } while(0)
#define F2ACC(d, a, b) asm("fma.rn.f32x2 %0, %1, %2, %0;" : "+l"(d) : "l"(a), "l"(b))

// ---------------- LayerNorm --------------------------------------------------
template<int W>
__global__ __launch_bounds__(256) void ln_kernel(const float* __restrict__ x,
        const float* __restrict__ w, const float* __restrict__ b,
        float* __restrict__ y)
{
    constexpr int E = W / 256;
    int row = blockIdx.x;
    const float* xr = x + (size_t)row * W;
    float v[E]; float s = 0.f, q = 0.f;
#pragma unroll
    for (int i = 0; i < E; i++) { v[i] = xr[threadIdx.x + 256*i]; s += v[i]; q += v[i]*v[i]; }
#pragma unroll
    for (int o = 16; o; o >>= 1) {
        s += __shfl_xor_sync(0xffffffffu, s, o);
        q += __shfl_xor_sync(0xffffffffu, q, o);
    }
    __shared__ float rs[8], rq[8];
    if ((threadIdx.x & 31) == 0) { rs[threadIdx.x>>5] = s; rq[threadIdx.x>>5] = q; }
    __syncthreads();
    float S = 0.f, Q = 0.f;
#pragma unroll
    for (int i = 0; i < 8; i++) { S += rs[i]; Q += rq[i]; }
    float mean = S / (float)W;
    float rstd = rsqrtf(Q / (float)W - mean*mean + 1e-5f);
    float* yr = y + (size_t)row * W;
#pragma unroll
    for (int i = 0; i < E; i++) {
        int c = threadIdx.x + 256*i;
        yr[c] = (v[i] - mean) * rstd * w[c] + b[c];
    }
}

// ---------------- fp32x2 SGEMM: 128x128x32, cp.async double buffer ----------
#define AST 36
#define GSMEM ((2*128*AST + 2*32*128) * 4)   // 69632 bytes
__global__ __launch_bounds__(256) void sgemm2(
    const float* __restrict__ A, const float* __restrict__ B,
    float* __restrict__ C, const float* __restrict__ addend,
    int M, int N, int K)
{
    extern __shared__ float dsm[];
    float* As = dsm;                       // 2 x 128 x AST
    float* Bs = dsm + 2*128*AST;           // 2 x 32 x 128
    const int tid = threadIdx.x;
    const int tx = tid & 15, ty = tid >> 4;
    const int m0 = blockIdx.x * 128, n0 = blockIdx.y * 128;
    const int NC = K >> 5;
    const uint32_t asb = smem_u32(As), bsb = smem_u32(Bs);

    u64 acc2[8][4];
#pragma unroll
    for (int i = 0; i < 8; i++)
#pragma unroll
        for (int j = 0; j < 4; j++) acc2[i][j] = 0ull;

    auto issue = [&](int c){
        int s = c & 1;
        int k0 = c << 5;
#pragma unroll
        for (int t = 0; t < 4; t++) {
            int id = tid + t * 256;
            int r = id >> 3, cc = id & 7;
            cp16(asb + s*18432 + r*144 + cc*16,
                 A + (size_t)(m0 + r) * K + k0 + cc*4, 16);
        }
#pragma unroll
        for (int t = 0; t < 4; t++) {
            int id = tid + t * 256;
            int k = id >> 5, n4 = id & 31;
            int n = n0 + n4 * 4;
            int ok = (n + 4 <= N);
            cp16(bsb + s*16384 + k*512 + n4*16,
                 B + (size_t)(k0 + k) * N + (ok ? n : 0), ok ? 16 : 0);
        }
    };

    issue(0); CP_COMMIT();

    for (int c = 0; c < NC; c++) {
        int s = c & 1;
        if (c + 1 < NC) { issue(c + 1); CP_COMMIT(); CP_WAIT1(); }
        else            { CP_WAIT0(); }
        __syncthreads();
        const float* as = As + s * (128*AST);
        const float* bs = Bs + s * (32*128);
#pragma unroll
        for (int kk = 0; kk < 32; kk++) {
            u64 a2[8];
#pragma unroll
            for (int i = 0; i < 4; i++) {
                float av0 = as[(ty*4 + i) * AST + kk];
                float av1 = as[(64 + ty*4 + i) * AST + kk];
                DUP2(a2[i], av0);
                DUP2(a2[4+i], av1);
            }
            ulonglong2 b01 = *(const ulonglong2*)&bs[kk*128 + tx*4];
            ulonglong2 b23 = *(const ulonglong2*)&bs[kk*128 + 64 + tx*4];
            u64 bv[4] = {b01.x, b01.y, b23.x, b23.y};
#pragma unroll
            for (int i = 0; i < 8; i++)
#pragma unroll
                for (int jp = 0; jp < 4; jp++)
                    F2ACC(acc2[i][jp], a2[i], bv[jp]);
        }
        __syncthreads();
    }

#pragma unroll
    for (int i = 0; i < 8; i++) {
        int m = m0 + ((i < 4) ? (ty*4 + i) : (64 + ty*4 + i - 4));
#pragma unroll
        for (int js = 0; js < 2; js++) {
            int col = n0 + js*64 + tx*4;
            if (col + 4 > N) continue;
            float4 v;
            UPK2(v.x, v.y, acc2[i][js*2+0]);
            UPK2(v.z, v.w, acc2[i][js*2+1]);
            if (addend) {
                float4 ad = *(const float4*)(addend + (size_t)m * N + col);
                v.x += ad.x; v.y += ad.y; v.z += ad.z; v.w += ad.w;
            }
            *(float4*)(C + (size_t)m * N + col) = v;
        }
    }
}

// ---------------- skinny GEMM: dbc cols 128..135 ----------------------------
__global__ __launch_bounds__(256) void skinny8(const float* __restrict__ Wx)
{
    __shared__ float sW[512*9];
    const int tid = threadIdx.x;
#pragma unroll
    for (int t = 0; t < 16; t++) {
        int idx = tid + t * 256;
        int k = idx >> 3, c = idx & 7;
        sW[k*9 + c] = Wx[(size_t)k * XPROJ + 128 + c];
    }
    __syncthreads();
    int row = blockIdx.x * 8 + (tid >> 5);
    int lane = tid & 31;
    float acc[8];
#pragma unroll
    for (int c = 0; c < 8; c++) acc[c] = 0.f;
    const float* ur = g_u + (size_t)row * DIN_;
#pragma unroll
    for (int i = 0; i < 16; i++) {
        int k = lane + i * 32;
        float uv = ur[k];
#pragma unroll
        for (int c = 0; c < 8; c++)
            acc[c] = fmaf(uv, sW[k*9 + c], acc[c]);
    }
#pragma unroll
    for (int o = 16; o; o >>= 1)
#pragma unroll
        for (int c = 0; c < 8; c++)
            acc[c] += __shfl_xor_sync(0xffffffffu, acc[c], o);
    if (lane == 0) {
#pragma unroll
        for (int c = 0; c < 8; c++)
            g_dbc[(size_t)row * XPROJ + 128 + c] = acc[c];
    }
}

// ---------------- depthwise conv3 + exact GELU ------------------------------
__global__ __launch_bounds__(256) void convgelu_k(const float* __restrict__ cw,
                                                  const float* __restrict__ cb)
{
    int idx = blockIdx.x * 256 + threadIdx.x;
    if (idx >= ROWS * DIN_) return;
    int c = idx & (DIN_ - 1);
    int l = (idx >> 9) & (LL - 1);
    float w0 = cw[c*3], w1 = cw[c*3+1], w2 = cw[c*3+2];
    float x = g_ur[idx] * w1 + cb[c];
    if (l > 0)      x += g_ur[idx - DIN_] * w0;
    if (l < LL - 1) x += g_ur[idx + DIN_] * w2;
    g_u[idx] = 0.5f * x * (1.f + erff(x * 0.7071067811865476f));
}

// ---------------- SSD phase A: fused dt prep + intra-chunk GEMMs ------------
__global__ __launch_bounds__(256,2) void ssdA(const float* __restrict__ dt_bias,
                                              const float* __restrict__ A_log)
{
    extern __shared__ float sm[];
    float* sB  = sm;            // 64 x 65
    float* sC  = sm + 4160;
    float* sX  = sm + 8320;
    float* sP  = sm + 12480;
    float* sdt = sm + 16640;
    float* sla = sdt + 64;
    float* sw  = sla + 64;
    const int c = blockIdx.x, h = blockIdx.y, b = blockIdx.z;
    const int tid = threadIdx.x;
    const int tx = tid & 15, ty = tid >> 4;
    const size_t r0 = (size_t)b * LL + c * CT;
    const int bh = b * HH + h;

#pragma unroll
    for (int i = 0; i < 4; i++) {
        int row = i * 16 + ty;
        const float* dr = g_dbc + (r0 + row) * XPROJ;
        float4 bv = *(const float4*)(dr + 8  + tx*4);
        float4 cv = *(const float4*)(dr + 72 + tx*4);
        float4 xv = *(const float4*)(g_u + (r0 + row)*DIN_ + h*64 + tx*4);
        sB[row*65 + tx*4+0]=bv.x; sB[row*65 + tx*4+1]=bv.y;
        sB[row*65 + tx*4+2]=bv.z; sB[row*65 + tx*4+3]=bv.w;
        sC[row*65 + tx*4+0]=cv.x; sC[row*65 + tx*4+1]=cv.y;
        sC[row*65 + tx*4+2]=cv.z; sC[row*65 + tx*4+3]=cv.w;
        sX[row*65 + tx*4+0]=xv.x; sX[row*65 + tx*4+1]=xv.y;
        sX[row*65 + tx*4+2]=xv.z; sX[row*65 + tx*4+3]=xv.w;
    }
    if (tid < 64) {
        float xx = g_dbc[(r0 + tid)*XPROJ + h] + dt_bias[h];
        float dt = (xx > 20.f) ? xx : log1pf(expf(xx));
        float la = -dt * expf(A_log[h]);
        int lane = tid & 31;
        float v = la;
#pragma unroll
        for (int o = 1; o < 32; o <<= 1) {
            float pv = __shfl_up_sync(0xffffffffu, v, o);
            if (lane >= o) v += pv;
        }
        sdt[tid] = dt;
        sla[tid] = v;
    }
    __syncthreads();
    if (tid >= 32 && tid < 64) sla[tid] += sla[31];
    __syncthreads();
    if (tid < 64) sw[tid] = sdt[tid] * __expf(sla[63] - sla[tid]);
    __syncthreads();

    // GEMM1: P[t][s] = C_t . B_s (f32x2 packed along s)
    u64 acc2[4][2];
#pragma unroll
    for (int i=0;i<4;i++) { acc2[i][0]=0ull; acc2[i][1]=0ull; }
#pragma unroll 8
    for (int n = 0; n < 64; n++) {
        u64 a2[4], b2[2];
#pragma unroll
        for (int i=0;i<4;i++) DUP2(a2[i], sC[(ty*4+i)*65 + n]);
        PK2(b2[0], sB[(tx*4+0)*65 + n], sB[(tx*4+1)*65 + n]);
        PK2(b2[1], sB[(tx*4+2)*65 + n], sB[(tx*4+3)*65 + n]);
#pragma unroll
        for (int i=0;i<4;i++) {
            F2ACC(acc2[i][0], a2[i], b2[0]);
            F2ACC(acc2[i][1], a2[i], b2[1]);
        }
    }
#pragma unroll
    for (int i=0;i<4;i++) {
        int t = ty*4 + i;
        float pv[4];
        UPK2(pv[0], pv[1], acc2[i][0]);
        UPK2(pv[2], pv[3], acc2[i][1]);
#pragma unroll
        for (int j=0;j<4;j++) {
            int s = tx*4 + j;
            sP[t*65 + s] = (s <= t) ? pv[j] * __expf(sla[t] - sla[s]) * sdt[s] : 0.f;
        }
    }
    __syncthreads();

    // GEMM2: y1[t][p] = P @ x (f32x2 packed along p)
#pragma unroll
    for (int i=0;i<4;i++) { acc2[i][0]=0ull; acc2[i][1]=0ull; }
#pragma unroll 8
    for (int s = 0; s < 64; s++) {
        u64 a2[4], b2[2];
#pragma unroll
        for (int i=0;i<4;i++) DUP2(a2[i], sP[(ty*4+i)*65 + s]);
        PK2(b2[0], sX[s*65 + tx*4+0], sX[s*65 + tx*4+1]);
        PK2(b2[1], sX[s*65 + tx*4+2], sX[s*65 + tx*4+3]);
#pragma unroll
        for (int i=0;i<4;i++) {
            F2ACC(acc2[i][0], a2[i], b2[0]);
            F2ACC(acc2[i][1], a2[i], b2[1]);
        }
    }
#pragma unroll
    for (int i=0;i<4;i++) {
        int t = ty*4 + i;
        float4 y;
        UPK2(y.x, y.y, acc2[i][0]);
        UPK2(y.z, y.w, acc2[i][1]);
        *(float4*)(g_yc + (r0 + t)*DIN_ + h*64 + tx*4) = y;
    }
    __syncthreads();

    // overwrite sP with weighted x
#pragma unroll
    for (int i = 0; i < 4; i++) {
        int row = i * 16 + ty;
        float wv = sw[row];
#pragma unroll
        for (int j = 0; j < 4; j++)
            sP[row*65 + tx*4 + j] = wv * sX[row*65 + tx*4 + j];
    }
    __syncthreads();

    // GEMM3: S[n][p] = sum_s B[s][n] * Xw[s][p] (f32x2 packed along p)
#pragma unroll
    for (int i=0;i<4;i++) { acc2[i][0]=0ull; acc2[i][1]=0ull; }
#pragma unroll 8
    for (int s = 0; s < 64; s++) {
        u64 a2[4], b2[2];
#pragma unroll
        for (int i=0;i<4;i++) DUP2(a2[i], sB[s*65 + ty*4 + i]);
        PK2(b2[0], sP[s*65 + tx*4+0], sP[s*65 + tx*4+1]);
        PK2(b2[1], sP[s*65 + tx*4+2], sP[s*65 + tx*4+3]);
#pragma unroll
        for (int i=0;i<4;i++) {
            F2ACC(acc2[i][0], a2[i], b2[0]);
            F2ACC(acc2[i][1], a2[i], b2[1]);
        }
    }
    size_t so = ((size_t)bh * NCH + c) * (NN*PP);
#pragma unroll
    for (int i=0;i<4;i++) {
        int n = ty*4 + i;
        float4 v;
        UPK2(v.x, v.y, acc2[i][0]);
        UPK2(v.z, v.w, acc2[i][1]);
        *(float4*)(g_S + so + n*64 + tx*4) = v;
    }
    if (tid < 64) g_la[((size_t)bh*NCH + c)*CT + tid] = sla[tid];
    if (tid == 0) g_pa[bh*NCH + c] = __expf(sla[63]);
}

// ---------------- SSD phase B: sequential chunk combine ---------------------
__global__ __launch_bounds__(256) void ssdB()
{
    int bh = blockIdx.x, tid = threadIdx.x;
    float h[16];
#pragma unroll
    for (int i=0;i<16;i++) h[i]=0.f;
    size_t base = (size_t)bh * NCH * (NN*PP);
    for (int c = 0; c < NCH; c++) {
        float pa = g_pa[bh*NCH + c];
        size_t cb = base + (size_t)c * (NN*PP);
#pragma unroll
        for (int i=0;i<16;i++) {
            size_t idx = cb + i*256 + tid;
            g_hin[idx] = h[i];
            h[i] = h[i]*pa + g_S[idx];
        }
    }
}

// ---------------- SSD phase C: state broadcast + epilogue -------------------
__global__ __launch_bounds__(256,2) void ssdC(const float* __restrict__ Ds)
{
    __shared__ float sCl[64*65];
    __shared__ float sH [64*65];
    __shared__ float sla2[64];
    const int c = blockIdx.x, h = blockIdx.y, b = blockIdx.z;
    const int tid = threadIdx.x;
    const int tx = tid & 15, ty = tid >> 4;
    const size_t r0 = (size_t)b * LL + c * CT;
    const int bh = b * HH + h;

    if (tid < 64) sla2[tid] = g_la[((size_t)bh*NCH + c)*CT + tid];
    __syncthreads();
#pragma unroll
    for (int i = 0; i < 4; i++) {
        int row = i * 16 + ty;
        float4 cv = *(const float4*)(g_dbc + (r0 + row)*XPROJ + 72 + tx*4);
        float e = __expf(sla2[row]);
        float4 hv = *(const float4*)(g_hin + ((size_t)bh*NCH + c)*(NN*PP) + row*64 + tx*4);
        sCl[row*65 + tx*4+0] = cv.x*e; sCl[row*65 + tx*4+1] = cv.y*e;
        sCl[row*65 + tx*4+2] = cv.z*e; sCl[row*65 + tx*4+3] = cv.w*e;
        sH [row*65 + tx*4+0] = hv.x;   sH [row*65 + tx*4+1] = hv.y;
        sH [row*65 + tx*4+2] = hv.z;   sH [row*65 + tx*4+3] = hv.w;
    }
    __syncthreads();

    u64 acc2[4][2];
#pragma unroll
    for (int i=0;i<4;i++) { acc2[i][0]=0ull; acc2[i][1]=0ull; }
#pragma unroll 8
    for (int n = 0; n < 64; n++) {
        u64 a2[4], b2[2];
#pragma unroll
        for (int i=0;i<4;i++) DUP2(a2[i], sCl[(ty*4+i)*65 + n]);
        PK2(b2[0], sH[n*65 + tx*4+0], sH[n*65 + tx*4+1]);
        PK2(b2[1], sH[n*65 + tx*4+2], sH[n*65 + tx*4+3]);
#pragma unroll
        for (int i=0;i<4;i++) {
            F2ACC(acc2[i][0], a2[i], b2[0]);
            F2ACC(acc2[i][1], a2[i], b2[1]);
        }
    }
    float dsh = Ds[h];
#pragma unroll
    for (int i=0;i<4;i++) {
        int t = ty*4 + i;
        float* yp = g_yc + (r0 + t)*DIN_ + h*64 + tx*4;
        float4 y1 = *(float4*)yp;
        float4 xv = *(const float4*)(g_u + (r0 + t)*DIN_ + h*64 + tx*4);
        float a0,a1,a2v,a3;
        UPK2(a0, a1, acc2[i][0]);
        UPK2(a2v, a3, acc2[i][1]);
        y1.x += a0 + dsh*xv.x;
        y1.y += a1 + dsh*xv.y;
        y1.z += a2v + dsh*xv.z;
        y1.w += a3 + dsh*xv.w;
        *(float4*)yp = y1;
    }
}

// ---------------- launch ----------------------------------------------------
extern "C" void kernel_launch(void* const* d_in, const int* in_sizes, int n_in,
                              void* d_out, int out_size)
{
    const float* src     = (const float*)d_in[0];
    const float* ln_w    = (const float*)d_in[1];
    const float* ln_b    = (const float*)d_in[2];
    const float* W_in    = (const float*)d_in[3];
    const float* conv_w  = (const float*)d_in[4];
    const float* conv_b  = (const float*)d_in[5];
    const float* W_xproj = (const float*)d_in[6];
    const float* dt_bias = (const float*)d_in[7];
    const float* A_log   = (const float*)d_in[8];
    const float* Ds      = (const float*)d_in[9];
    const float* oln_w   = (const float*)d_in[10];
    const float* oln_b   = (const float*)d_in[11];
    const float* W_out   = (const float*)d_in[12];
    float* out = (float*)d_out;

    float *p_xln, *p_ur, *p_u, *p_dbc, *p_yc, *p_yln;
    cudaGetSymbolAddress((void**)&p_xln, g_xln);
    cudaGetSymbolAddress((void**)&p_ur,  g_ur);
    cudaGetSymbolAddress((void**)&p_u,   g_u);
    cudaGetSymbolAddress((void**)&p_dbc, g_dbc);
    cudaGetSymbolAddress((void**)&p_yc,  g_yc);
    cudaGetSymbolAddress((void**)&p_yln, g_yln);

    const int ASMEM = 67328;
    cudaFuncSetAttribute(ssdA, cudaFuncAttributeMaxDynamicSharedMemorySize, ASMEM);
    cudaFuncSetAttribute(sgemm2, cudaFuncAttributeMaxDynamicSharedMemorySize, GSMEM);

    // 1) x = LN(src)
    ln_kernel<DD><<<ROWS, 256>>>(src, ln_w, ln_b, p_xln);
    // 2) ur = x @ W_in
    sgemm2<<<dim3(ROWS/128, DIN_/128), 256, GSMEM>>>(p_xln, W_in, p_ur, nullptr,
                                                     ROWS, DIN_, DD);
    // 3) u = gelu(conv3(ur)+b)
    convgelu_k<<<(ROWS*DIN_)/256, 256>>>(conv_w, conv_b);
    // 4) dbc = u @ W_xproj: main 128 cols + skinny last 8
    sgemm2<<<dim3(ROWS/128, 1), 256, GSMEM>>>(p_u, W_xproj, p_dbc, nullptr,
                                              ROWS, XPROJ, DIN_);
    skinny8<<<ROWS/8, 256>>>(W_xproj);
    // 5) chunked scan
    ssdA<<<dim3(NCH, HH, BB), 256, ASMEM>>>(dt_bias, A_log);
    ssdB<<<BB*HH, 256>>>();
    ssdC<<<dim3(NCH, HH, BB), 256>>>(Ds);
    // 6) yln = LN(yc)
    ln_kernel<DIN_><<<ROWS, 256>>>(p_yc, oln_w, oln_b, p_yln);
    // 7) out = src + yln @ W_out
    sgemm2<<<dim3(ROWS/128, DD/128), 256, GSMEM>>>(p_yln, W_out, out, src,
                                                   ROWS, DD, DIN_);
}

// round 11
// speedup vs baseline: 2.7927x; 1.2630x over previous
#include <cuda_runtime.h>
#include <cuda_bf16.h>
#include <math.h>
#include <stdint.h>

#define BB   8
#define LL   2048
#define DD   256
#define DIN_ 512
#define NN   64
#define PP   64
#define HH   8
#define ROWS (BB*LL)          // 16384
#define XPROJ (HH + 2*NN)     // 136
#define NCH  32
#define CT   64

typedef unsigned long long u64;

// ---------------- scratch (device globals) ---------------------------------
__device__ __nv_bfloat16 g_xh[ROWS*DD],   g_xl[ROWS*DD];
__device__ float         g_ur [ROWS*DIN_];
__device__ float         g_u  [ROWS*DIN_];
__device__ __nv_bfloat16 g_uh[ROWS*DIN_], g_ul[ROWS*DIN_];
__device__ float         g_dbc[ROWS*XPROJ];
__device__ float         g_yc [ROWS*DIN_];
__device__ __nv_bfloat16 g_yh[ROWS*DIN_], g_yl[ROWS*DIN_];
__device__ float         g_S  [BB*HH*NCH*NN*PP];
__device__ float         g_hin[BB*HH*NCH*NN*PP];
__device__ float         g_la [BB*HH*NCH*CT];
__device__ float         g_pa [BB*HH*NCH];
// transposed+split weights Wt[n*K+k]
__device__ __nv_bfloat16 g_w1h[DIN_*DD],    g_w1l[DIN_*DD];
__device__ __nv_bfloat16 g_w2h[XPROJ*DIN_], g_w2l[XPROJ*DIN_];
__device__ __nv_bfloat16 g_w3h[DD*DIN_],    g_w3l[DD*DIN_];

// ---------------- helpers ---------------------------------------------------
__device__ __forceinline__ uint32_t smem_u32(const void* p){
    uint32_t a;
    asm("{ .reg .u64 t; cvta.to.shared.u64 t, %1; cvt.u32.u64 %0, t; }" : "=r"(a) : "l"(p));
    return a;
}
__device__ __forceinline__ void cp16(uint32_t dst, const void* src, int sz){
    asm volatile("cp.async.ca.shared.global [%0], [%1], 16, %2;"
                 :: "r"(dst), "l"(src), "r"(sz) : "memory");
}
#define CP_COMMIT() asm volatile("cp.async.commit_group;" ::: "memory")
#define CP_WAIT1()  asm volatile("cp.async.wait_group 1;" ::: "memory")
#define CP_WAIT0()  asm volatile("cp.async.wait_group 0;" ::: "memory")

#define LDSM4(r, a) asm volatile( \
    "ldmatrix.sync.aligned.m8n8.x4.shared.b16 {%0,%1,%2,%3}, [%4];" \
    : "=r"((r)[0]),"=r"((r)[1]),"=r"((r)[2]),"=r"((r)[3]) : "r"(a))

__device__ __forceinline__ void mma_bf16(float* d, const uint32_t* a, const uint32_t* b){
    asm volatile("mma.sync.aligned.m16n8k16.row.col.f32.bf16.bf16.f32 "
        "{%0,%1,%2,%3}, {%4,%5,%6,%7}, {%8,%9}, {%0,%1,%2,%3};"
        : "+f"(d[0]), "+f"(d[1]), "+f"(d[2]), "+f"(d[3])
        : "r"(a[0]), "r"(a[1]), "r"(a[2]), "r"(a[3]), "r"(b[0]), "r"(b[1]));
}

// packed f32x2 (for SSD kernels)
#define PK2(d, lo, hi) asm("mov.b64 %0, {%1,%2};" : "=l"(d) : "r"(__float_as_uint(lo)), "r"(__float_as_uint(hi)))
#define DUP2(d, x)     asm("mov.b64 %0, {%1,%1};" : "=l"(d) : "r"(__float_as_uint(x)))
#define UPK2(lo, hi, v) do { uint32_t _a,_b; asm("mov.b64 {%0,%1}, %2;" : "=r"(_a), "=r"(_b) : "l"(v)); lo=__uint_as_float(_a); hi=__uint_as_float(_b); } while(0)
#define F2ACC(d, a, b) asm("fma.rn.f32x2 %0, %1, %2, %0;" : "+l"(d) : "l"(a), "l"(b))

// ---------------- weight prep: transpose + bf16 hi/lo split ----------------
__global__ __launch_bounds__(256) void wprep(const float* __restrict__ W,
        __nv_bfloat16* __restrict__ oh, __nv_bfloat16* __restrict__ ol, int K, int N)
{
    int idx = blockIdx.x * 256 + threadIdx.x;
    if (idx >= K * N) return;
    int n = idx / K, k = idx - n * K;
    float v = W[(size_t)k * N + n];
    __nv_bfloat16 hh = __float2bfloat16(v);
    oh[idx] = hh;
    ol[idx] = __float2bfloat16(v - __bfloat162float(hh));
}

// ---------------- LayerNorm -> bf16 hi/lo ----------------------------------
template<int W>
__global__ __launch_bounds__(256) void ln_bf(const float* __restrict__ x,
        const float* __restrict__ w, const float* __restrict__ b,
        __nv_bfloat16* __restrict__ yh, __nv_bfloat16* __restrict__ yl)
{
    constexpr int E = W / 256;
    int row = blockIdx.x;
    const float* xr = x + (size_t)row * W;
    float v[E]; float s = 0.f, q = 0.f;
#pragma unroll
    for (int i = 0; i < E; i++) { v[i] = xr[threadIdx.x + 256*i]; s += v[i]; q += v[i]*v[i]; }
#pragma unroll
    for (int o = 16; o; o >>= 1) {
        s += __shfl_xor_sync(0xffffffffu, s, o);
        q += __shfl_xor_sync(0xffffffffu, q, o);
    }
    __shared__ float rs[8], rq[8];
    if ((threadIdx.x & 31) == 0) { rs[threadIdx.x>>5] = s; rq[threadIdx.x>>5] = q; }
    __syncthreads();
    float S = 0.f, Q = 0.f;
#pragma unroll
    for (int i = 0; i < 8; i++) { S += rs[i]; Q += rq[i]; }
    float mean = S / (float)W;
    float rstd = rsqrtf(Q / (float)W - mean*mean + 1e-5f);
#pragma unroll
    for (int i = 0; i < E; i++) {
        int c = threadIdx.x + 256*i;
        float o = (v[i] - mean) * rstd * w[c] + b[c];
        __nv_bfloat16 hh = __float2bfloat16(o);
        yh[(size_t)row*W + c] = hh;
        yl[(size_t)row*W + c] = __float2bfloat16(o - __bfloat162float(hh));
    }
}

// ---------------- HMMA bf16-split GEMM (ldmatrix feed) ----------------------
// C = Ah@Bh^T + Ah@Bl^T + Al@Bh^T (+addend). A[M,K] bf16 row-major (hi/lo),
// B[N,K] bf16 row-major (pre-transposed weights). CTA 128x128x32, 8 warps.
#define HMAT   10240            // 128 rows x 80B per matrix
#define HSTAGE 40960            // 4 matrices
#define HSMEM  81920            // double buffered
__global__ __launch_bounds__(256) void hgemm(
    const __nv_bfloat16* __restrict__ Ah, const __nv_bfloat16* __restrict__ Al,
    const __nv_bfloat16* __restrict__ Bh, const __nv_bfloat16* __restrict__ Bl,
    float* __restrict__ C, const float* __restrict__ addend,
    int M, int N, int K)
{
    extern __shared__ char hsm[];
    const uint32_t sb = smem_u32(hsm);
    const int tid = threadIdx.x, wid = tid >> 5, lane = tid & 31;
    const int m0 = blockIdx.x * 128, n0 = blockIdx.y * 128;
    const int wm = (wid >> 1) * 32, wn = (wid & 1) * 64;
    const int NC = K >> 5;

    float acc[2][8][4];
#pragma unroll
    for (int i = 0; i < 2; i++)
#pragma unroll
        for (int j = 0; j < 8; j++)
#pragma unroll
            for (int q = 0; q < 4; q++) acc[i][j][q] = 0.f;

    auto issue = [&](int c){
        int s = c & 1;
        int k0 = c << 5;
#pragma unroll
        for (int i = 0; i < 8; i++) {
            int idx = tid + i * 256;
            int mat = idx >> 9, w = idx & 511, row = w >> 2, cc = w & 3;
            uint32_t dst = sb + s*HSTAGE + mat*HMAT + row*80 + cc*16;
            if (mat == 0)
                cp16(dst, Ah + (size_t)(m0 + row) * K + k0 + cc*8, 16);
            else if (mat == 1)
                cp16(dst, Al + (size_t)(m0 + row) * K + k0 + cc*8, 16);
            else {
                int n = n0 + row;
                int ok = (n < N);
                const __nv_bfloat16* Bp = (mat == 2) ? Bh : Bl;
                cp16(dst, Bp + (size_t)(ok ? n : 0) * K + k0 + cc*8, ok ? 16 : 0);
            }
        }
    };

    // ldmatrix lane addressing
    const int rA  = wm + (lane & 15);
    const int kAo = (lane >> 4) * 16;                         // +16B for k8-15
    const int rB  = wn + (lane & 7) + ((lane >> 4) & 1) * 8;  // n row
    const int kBo = ((lane >> 3) & 1) * 16;

    issue(0); CP_COMMIT();

    for (int c = 0; c < NC; c++) {
        int s = c & 1;
        if (c + 1 < NC) { issue(c + 1); CP_COMMIT(); CP_WAIT1(); }
        else            { CP_WAIT0(); }
        __syncthreads();
        uint32_t st = sb + s * HSTAGE;
#pragma unroll
        for (int ks = 0; ks < 2; ks++) {        // two k16 halves (byte off 0/32)
            int ksb = ks * 32;
            uint32_t ah[2][4], al[2][4];
            uint32_t aAdr = st + rA*80 + ksb + kAo;
            LDSM4(ah[0], aAdr);
            LDSM4(ah[1], aAdr + 16*80);
            LDSM4(al[0], aAdr + HMAT);
            LDSM4(al[1], aAdr + HMAT + 16*80);
            uint32_t bh[8][2], bl[8][2];
#pragma unroll
            for (int jp = 0; jp < 4; jp++) {
                uint32_t r4[4];
                uint32_t bAdr = st + 2*HMAT + (rB + jp*16)*80 + ksb + kBo;
                LDSM4(r4, bAdr);
                bh[jp*2  ][0]=r4[0]; bh[jp*2  ][1]=r4[1];
                bh[jp*2+1][0]=r4[2]; bh[jp*2+1][1]=r4[3];
                LDSM4(r4, bAdr + HMAT);
                bl[jp*2  ][0]=r4[0]; bl[jp*2  ][1]=r4[1];
                bl[jp*2+1][0]=r4[2]; bl[jp*2+1][1]=r4[3];
            }
#pragma unroll
            for (int i = 0; i < 2; i++)
#pragma unroll
                for (int j = 0; j < 8; j++) {
                    mma_bf16(acc[i][j], ah[i], bh[j]);
                    mma_bf16(acc[i][j], ah[i], bl[j]);
                    mma_bf16(acc[i][j], al[i], bh[j]);
                }
        }
        __syncthreads();
    }

    // epilogue (mma C layout)
    const int g = lane >> 2, tg = lane & 3;
#pragma unroll
    for (int i = 0; i < 2; i++) {
#pragma unroll
        for (int j = 0; j < 8; j++) {
            int col = n0 + wn + j*8 + tg*2;
            if (col >= N) continue;
            int mA = m0 + wm + i*16 + g;
            int mB = mA + 8;
            float2 v0 = make_float2(acc[i][j][0], acc[i][j][1]);
            float2 v1 = make_float2(acc[i][j][2], acc[i][j][3]);
            if (addend) {
                float2 a0 = *(const float2*)(addend + (size_t)mA * N + col);
                float2 a1 = *(const float2*)(addend + (size_t)mB * N + col);
                v0.x += a0.x; v0.y += a0.y; v1.x += a1.x; v1.y += a1.y;
            }
            *(float2*)(C + (size_t)mA * N + col) = v0;
            *(float2*)(C + (size_t)mB * N + col) = v1;
        }
    }
}

// ---------------- skinny GEMM: dbc cols 128..135 ----------------------------
__global__ __launch_bounds__(256) void skinny8(const float* __restrict__ Wx)
{
    __shared__ float sW[512*9];
    const int tid = threadIdx.x;
#pragma unroll
    for (int t = 0; t < 16; t++) {
        int idx = tid + t * 256;
        int k = idx >> 3, c = idx & 7;
        sW[k*9 + c] = Wx[(size_t)k * XPROJ + 128 + c];
    }
    __syncthreads();
    int row = blockIdx.x * 8 + (tid >> 5);
    int lane = tid & 31;
    float acc[8];
#pragma unroll
    for (int c = 0; c < 8; c++) acc[c] = 0.f;
    const float* ur = g_u + (size_t)row * DIN_;
#pragma unroll
    for (int i = 0; i < 16; i++) {
        int k = lane + i * 32;
        float uv = ur[k];
#pragma unroll
        for (int c = 0; c < 8; c++)
            acc[c] = fmaf(uv, sW[k*9 + c], acc[c]);
    }
#pragma unroll
    for (int o = 16; o; o >>= 1)
#pragma unroll
        for (int c = 0; c < 8; c++)
            acc[c] += __shfl_xor_sync(0xffffffffu, acc[c], o);
    if (lane == 0) {
#pragma unroll
        for (int c = 0; c < 8; c++)
            g_dbc[(size_t)row * XPROJ + 128 + c] = acc[c];
    }
}

// ---------------- depthwise conv3 + GELU -> fp32 + bf16 hi/lo ---------------
__global__ __launch_bounds__(256) void convgelu_k(const float* __restrict__ cw,
                                                  const float* __restrict__ cb)
{
    int idx = blockIdx.x * 256 + threadIdx.x;
    if (idx >= ROWS * DIN_) return;
    int c = idx & (DIN_ - 1);
    int l = (idx >> 9) & (LL - 1);
    float w0 = cw[c*3], w1 = cw[c*3+1], w2 = cw[c*3+2];
    float x = g_ur[idx] * w1 + cb[c];
    if (l > 0)      x += g_ur[idx - DIN_] * w0;
    if (l < LL - 1) x += g_ur[idx + DIN_] * w2;
    float g = 0.5f * x * (1.f + erff(x * 0.7071067811865476f));
    g_u[idx] = g;
    __nv_bfloat16 hh = __float2bfloat16(g);
    g_uh[idx] = hh;
    g_ul[idx] = __float2bfloat16(g - __bfloat162float(hh));
}

// ---------------- SSD phase A: fused dt prep + intra-chunk GEMMs ------------
__global__ __launch_bounds__(256,2) void ssdA(const float* __restrict__ dt_bias,
                                              const float* __restrict__ A_log)
{
    extern __shared__ float sm[];
    float* sB  = sm;            // 64 x 65
    float* sC  = sm + 4160;
    float* sX  = sm + 8320;
    float* sP  = sm + 12480;
    float* sdt = sm + 16640;
    float* sla = sdt + 64;
    float* sw  = sla + 64;
    const int c = blockIdx.x, h = blockIdx.y, b = blockIdx.z;
    const int tid = threadIdx.x;
    const int tx = tid & 15, ty = tid >> 4;
    const size_t r0 = (size_t)b * LL + c * CT;
    const int bh = b * HH + h;

#pragma unroll
    for (int i = 0; i < 4; i++) {
        int row = i * 16 + ty;
        const float* dr = g_dbc + (r0 + row) * XPROJ;
        float4 bv = *(const float4*)(dr + 8  + tx*4);
        float4 cv = *(const float4*)(dr + 72 + tx*4);
        float4 xv = *(const float4*)(g_u + (r0 + row)*DIN_ + h*64 + tx*4);
        sB[row*65 + tx*4+0]=bv.x; sB[row*65 + tx*4+1]=bv.y;
        sB[row*65 + tx*4+2]=bv.z; sB[row*65 + tx*4+3]=bv.w;
        sC[row*65 + tx*4+0]=cv.x; sC[row*65 + tx*4+1]=cv.y;
        sC[row*65 + tx*4+2]=cv.z; sC[row*65 + tx*4+3]=cv.w;
        sX[row*65 + tx*4+0]=xv.x; sX[row*65 + tx*4+1]=xv.y;
        sX[row*65 + tx*4+2]=xv.z; sX[row*65 + tx*4+3]=xv.w;
    }
    if (tid < 64) {
        float xx = g_dbc[(r0 + tid)*XPROJ + h] + dt_bias[h];
        float dt = (xx > 20.f) ? xx : log1pf(expf(xx));
        float la = -dt * expf(A_log[h]);
        int lane = tid & 31;
        float v = la;
#pragma unroll
        for (int o = 1; o < 32; o <<= 1) {
            float pv = __shfl_up_sync(0xffffffffu, v, o);
            if (lane >= o) v += pv;
        }
        sdt[tid] = dt;
        sla[tid] = v;
    }
    __syncthreads();
    if (tid >= 32 && tid < 64) sla[tid] += sla[31];
    __syncthreads();
    if (tid < 64) sw[tid] = sdt[tid] * __expf(sla[63] - sla[tid]);
    __syncthreads();

    u64 acc2[4][2];
#pragma unroll
    for (int i=0;i<4;i++) { acc2[i][0]=0ull; acc2[i][1]=0ull; }
#pragma unroll 8
    for (int n = 0; n < 64; n++) {
        u64 a2[4], b2[2];
#pragma unroll
        for (int i=0;i<4;i++) DUP2(a2[i], sC[(ty*4+i)*65 + n]);
        PK2(b2[0], sB[(tx*4+0)*65 + n], sB[(tx*4+1)*65 + n]);
        PK2(b2[1], sB[(tx*4+2)*65 + n], sB[(tx*4+3)*65 + n]);
#pragma unroll
        for (int i=0;i<4;i++) {
            F2ACC(acc2[i][0], a2[i], b2[0]);
            F2ACC(acc2[i][1], a2[i], b2[1]);
        }
    }
#pragma unroll
    for (int i=0;i<4;i++) {
        int t = ty*4 + i;
        float pv[4];
        UPK2(pv[0], pv[1], acc2[i][0]);
        UPK2(pv[2], pv[3], acc2[i][1]);
#pragma unroll
        for (int j=0;j<4;j++) {
            int s = tx*4 + j;
            sP[t*65 + s] = (s <= t) ? pv[j] * __expf(sla[t] - sla[s]) * sdt[s] : 0.f;
        }
    }
    __syncthreads();

#pragma unroll
    for (int i=0;i<4;i++) { acc2[i][0]=0ull; acc2[i][1]=0ull; }
#pragma unroll 8
    for (int s = 0; s < 64; s++) {
        u64 a2[4], b2[2];
#pragma unroll
        for (int i=0;i<4;i++) DUP2(a2[i], sP[(ty*4+i)*65 + s]);
        PK2(b2[0], sX[s*65 + tx*4+0], sX[s*65 + tx*4+1]);
        PK2(b2[1], sX[s*65 + tx*4+2], sX[s*65 + tx*4+3]);
#pragma unroll
        for (int i=0;i<4;i++) {
            F2ACC(acc2[i][0], a2[i], b2[0]);
            F2ACC(acc2[i][1], a2[i], b2[1]);
        }
    }
#pragma unroll
    for (int i=0;i<4;i++) {
        int t = ty*4 + i;
        float4 y;
        UPK2(y.x, y.y, acc2[i][0]);
        UPK2(y.z, y.w, acc2[i][1]);
        *(float4*)(g_yc + (r0 + t)*DIN_ + h*64 + tx*4) = y;
    }
    __syncthreads();

#pragma unroll
    for (int i = 0; i < 4; i++) {
        int row = i * 16 + ty;
        float wv = sw[row];
#pragma unroll
        for (int j = 0; j < 4; j++)
            sP[row*65 + tx*4 + j] = wv * sX[row*65 + tx*4 + j];
    }
    __syncthreads();

#pragma unroll
    for (int i=0;i<4;i++) { acc2[i][0]=0ull; acc2[i][1]=0ull; }
#pragma unroll 8
    for (int s = 0; s < 64; s++) {
        u64 a2[4], b2[2];
#pragma unroll
        for (int i=0;i<4;i++) DUP2(a2[i], sB[s*65 + ty*4 + i]);
        PK2(b2[0], sP[s*65 + tx*4+0], sP[s*65 + tx*4+1]);
        PK2(b2[1], sP[s*65 + tx*4+2], sP[s*65 + tx*4+3]);
#pragma unroll
        for (int i=0;i<4;i++) {
            F2ACC(acc2[i][0], a2[i], b2[0]);
            F2ACC(acc2[i][1], a2[i], b2[1]);
        }
    }
    size_t so = ((size_t)bh * NCH + c) * (NN*PP);
#pragma unroll
    for (int i=0;i<4;i++) {
        int n = ty*4 + i;
        float4 v;
        UPK2(v.x, v.y, acc2[i][0]);
        UPK2(v.z, v.w, acc2[i][1]);
        *(float4*)(g_S + so + n*64 + tx*4) = v;
    }
    if (tid < 64) g_la[((size_t)bh*NCH + c)*CT + tid] = sla[tid];
    if (tid == 0) g_pa[bh*NCH + c] = __expf(sla[63]);
}

// ---------------- SSD phase B ------------------------------------------------
__global__ __launch_bounds__(256) void ssdB()
{
    int bh = blockIdx.x, tid = threadIdx.x;
    float h[16];
#pragma unroll
    for (int i=0;i<16;i++) h[i]=0.f;
    size_t base = (size_t)bh * NCH * (NN*PP);
    for (int c = 0; c < NCH; c++) {
        float pa = g_pa[bh*NCH + c];
        size_t cb = base + (size_t)c * (NN*PP);
#pragma unroll
        for (int i=0;i<16;i++) {
            size_t idx = cb + i*256 + tid;
            g_hin[idx] = h[i];
            h[i] = h[i]*pa + g_S[idx];
        }
    }
}

// ---------------- SSD phase C ------------------------------------------------
__global__ __launch_bounds__(256,2) void ssdC(const float* __restrict__ Ds)
{
    __shared__ float sCl[64*65];
    __shared__ float sH [64*65];
    __shared__ float sla2[64];
    const int c = blockIdx.x, h = blockIdx.y, b = blockIdx.z;
    const int tid = threadIdx.x;
    const int tx = tid & 15, ty = tid >> 4;
    const size_t r0 = (size_t)b * LL + c * CT;
    const int bh = b * HH + h;

    if (tid < 64) sla2[tid] = g_la[((size_t)bh*NCH + c)*CT + tid];
    __syncthreads();
#pragma unroll
    for (int i = 0; i < 4; i++) {
        int row = i * 16 + ty;
        float4 cv = *(const float4*)(g_dbc + (r0 + row)*XPROJ + 72 + tx*4);
        float e = __expf(sla2[row]);
        float4 hv = *(const float4*)(g_hin + ((size_t)bh*NCH + c)*(NN*PP) + row*64 + tx*4);
        sCl[row*65 + tx*4+0] = cv.x*e; sCl[row*65 + tx*4+1] = cv.y*e;
        sCl[row*65 + tx*4+2] = cv.z*e; sCl[row*65 + tx*4+3] = cv.w*e;
        sH [row*65 + tx*4+0] = hv.x;   sH [row*65 + tx*4+1] = hv.y;
        sH [row*65 + tx*4+2] = hv.z;   sH [row*65 + tx*4+3] = hv.w;
    }
    __syncthreads();

    u64 acc2[4][2];
#pragma unroll
    for (int i=0;i<4;i++) { acc2[i][0]=0ull; acc2[i][1]=0ull; }
#pragma unroll 8
    for (int n = 0; n < 64; n++) {
        u64 a2[4], b2[2];
#pragma unroll
        for (int i=0;i<4;i++) DUP2(a2[i], sCl[(ty*4+i)*65 + n]);
        PK2(b2[0], sH[n*65 + tx*4+0], sH[n*65 + tx*4+1]);
        PK2(b2[1], sH[n*65 + tx*4+2], sH[n*65 + tx*4+3]);
#pragma unroll
        for (int i=0;i<4;i++) {
            F2ACC(acc2[i][0], a2[i], b2[0]);
            F2ACC(acc2[i][1], a2[i], b2[1]);
        }
    }
    float dsh = Ds[h];
#pragma unroll
    for (int i=0;i<4;i++) {
        int t = ty*4 + i;
        float* yp = g_yc + (r0 + t)*DIN_ + h*64 + tx*4;
        float4 y1 = *(float4*)yp;
        float4 xv = *(const float4*)(g_u + (r0 + t)*DIN_ + h*64 + tx*4);
        float a0,a1,a2v,a3;
        UPK2(a0, a1, acc2[i][0]);
        UPK2(a2v, a3, acc2[i][1]);
        y1.x += a0 + dsh*xv.x;
        y1.y += a1 + dsh*xv.y;
        y1.z += a2v + dsh*xv.z;
        y1.w += a3 + dsh*xv.w;
        *(float4*)yp = y1;
    }
}

// ---------------- launch ----------------------------------------------------
extern "C" void kernel_launch(void* const* d_in, const int* in_sizes, int n_in,
                              void* d_out, int out_size)
{
    const float* src     = (const float*)d_in[0];
    const float* ln_w    = (const float*)d_in[1];
    const float* ln_b    = (const float*)d_in[2];
    const float* W_in    = (const float*)d_in[3];
    const float* conv_w  = (const float*)d_in[4];
    const float* conv_b  = (const float*)d_in[5];
    const float* W_xproj = (const float*)d_in[6];
    const float* dt_bias = (const float*)d_in[7];
    const float* A_log   = (const float*)d_in[8];
    const float* Ds      = (const float*)d_in[9];
    const float* oln_w   = (const float*)d_in[10];
    const float* oln_b   = (const float*)d_in[11];
    const float* W_out   = (const float*)d_in[12];
    float* out = (float*)d_out;

    __nv_bfloat16 *p_xh,*p_xl,*p_uh,*p_ul,*p_yh,*p_yl;
    __nv_bfloat16 *p_w1h,*p_w1l,*p_w2h,*p_w2l,*p_w3h,*p_w3l;
    float *p_ur,*p_dbc,*p_yc;
    cudaGetSymbolAddress((void**)&p_xh, g_xh);   cudaGetSymbolAddress((void**)&p_xl, g_xl);
    cudaGetSymbolAddress((void**)&p_uh, g_uh);   cudaGetSymbolAddress((void**)&p_ul, g_ul);
    cudaGetSymbolAddress((void**)&p_yh, g_yh);   cudaGetSymbolAddress((void**)&p_yl, g_yl);
    cudaGetSymbolAddress((void**)&p_w1h, g_w1h); cudaGetSymbolAddress((void**)&p_w1l, g_w1l);
    cudaGetSymbolAddress((void**)&p_w2h, g_w2h); cudaGetSymbolAddress((void**)&p_w2l, g_w2l);
    cudaGetSymbolAddress((void**)&p_w3h, g_w3h); cudaGetSymbolAddress((void**)&p_w3l, g_w3l);
    cudaGetSymbolAddress((void**)&p_ur, g_ur);
    cudaGetSymbolAddress((void**)&p_dbc, g_dbc);
    cudaGetSymbolAddress((void**)&p_yc, g_yc);

    const int ASMEM = 67328;
    cudaFuncSetAttribute(ssdA, cudaFuncAttributeMaxDynamicSharedMemorySize, ASMEM);
    cudaFuncSetAttribute(hgemm, cudaFuncAttributeMaxDynamicSharedMemorySize, HSMEM);

    // weight prep
    wprep<<<(DD*DIN_ + 255)/256, 256>>>(W_in,    p_w1h, p_w1l, DD,   DIN_);
    wprep<<<(DIN_*XPROJ + 255)/256, 256>>>(W_xproj, p_w2h, p_w2l, DIN_, XPROJ);
    wprep<<<(DIN_*DD + 255)/256, 256>>>(W_out,   p_w3h, p_w3l, DIN_, DD);

    // 1) LN1 -> bf16 hi/lo
    ln_bf<DD><<<ROWS, 256>>>(src, ln_w, ln_b, p_xh, p_xl);
    // 2) ur = x @ W_in  (N=512, K=256)
    hgemm<<<dim3(ROWS/128, 4), 256, HSMEM>>>(p_xh, p_xl, p_w1h, p_w1l, p_ur, nullptr,
                                             ROWS, DIN_, DD);
    // 3) u = gelu(conv3(ur)+b)
    convgelu_k<<<(ROWS*DIN_)/256, 256>>>(conv_w, conv_b);
    // 4) dbc = u @ W_xproj: main 128 cols via HMMA, last 8 via skinny
    hgemm<<<dim3(ROWS/128, 1), 256, HSMEM>>>(p_uh, p_ul, p_w2h, p_w2l, p_dbc, nullptr,
                                             ROWS, XPROJ, DIN_);
    skinny8<<<ROWS/8, 256>>>(W_xproj);
    // 5) chunked scan
    ssdA<<<dim3(NCH, HH, BB), 256, ASMEM>>>(dt_bias, A_log);
    ssdB<<<BB*HH, 256>>>();
    ssdC<<<dim3(NCH, HH, BB), 256>>>(Ds);
    // 6) oln -> bf16 hi/lo
    ln_bf<DIN_><<<ROWS, 256>>>(p_yc, oln_w, oln_b, p_yh, p_yl);
    // 7) out = src + yln @ W_out (N=256, K=512)
    hgemm<<<dim3(ROWS/128, 2), 256, HSMEM>>>(p_yh, p_yl, p_w3h, p_w3l, out, src,
                                             ROWS, DD, DIN_);
}